// round 12
// baseline (speedup 1.0000x reference)
#include <cuda_runtime.h>
#include <cuda_bf16.h>
#include <cstdint>

#define N_NODES 100000
#define N_PAD   100096            // 782 * 128
#define N_EDGES 1250000
#define D_IN    64
#define OUT_COLS 300
#define WC_COLS 320
#define WC_ROWS 192
#define SCAN_BS 1024
#define SCAN_NB ((N_NODES + SCAN_BS - 1) / SCAN_BS)   // 98

// ---------------- scratch (device globals) ----------------
__device__ __align__(16) float  g_dis[N_NODES];
__device__ __align__(16) int    g_cnt[N_NODES];
__device__ __align__(16) int    g_scan[N_NODES];
__device__ __align__(16) int    g_bsum[SCAN_NB];
__device__ __align__(16) int    g_boff[SCAN_NB];
__device__ __align__(16) int    g_off[N_NODES + 1];
__device__ __align__(16) int    g_cur[N_NODES];
__device__ __align__(16) float2 g_pack[N_EDGES];
__device__ __align__(16) float  g_T1[N_NODES * D_IN];
__device__ __align__(16) float  g_T2[N_NODES * D_IN];
__device__ __align__(16) float  g_WcT[WC_COLS * WC_ROWS];          // [col][k] fp32
__device__ __align__(16) __nv_bfloat16 g_WTh[WC_COLS * WC_ROWS];   // bf16 hi
__device__ __align__(16) __nv_bfloat16 g_WTl[WC_COLS * WC_ROWS];   // bf16 lo
__device__ __align__(16) __nv_bfloat16 g_Ah[3 * N_PAD * D_IN];     // x|T1|T2 bf16 hi (padded rows)
__device__ __align__(16) __nv_bfloat16 g_Al[3 * N_PAD * D_IN];     // lo
__device__ __align__(16) float  g_bias[WC_COLS];
__device__ int g_is64;

// ---------------- edge dtype handling ----------------
__global__ void detect_dtype_kernel(const int* __restrict__ ei32) {
    __shared__ int nz;
    if (threadIdx.x == 0) nz = 0;
    __syncthreads();
    int w = 2 * threadIdx.x + 1;
    if (ei32[w] != 0) atomicAdd(&nz, 1);
    __syncthreads();
    if (threadIdx.x == 0) g_is64 = (nz == 0) ? 1 : 0;
}
__device__ __forceinline__ void load_edge(const void* ei, int e, unsigned& r, unsigned& c) {
    if (g_is64) {
        const long long* p = (const long long*)ei;
        r = (unsigned)(int)p[e];  c = (unsigned)(int)p[N_EDGES + e];
    } else {
        const int* p = (const int*)ei;
        r = (unsigned)p[e];       c = (unsigned)p[N_EDGES + e];
    }
}

// ---------------- graph pipeline (identical to passing R11) ----------------
__global__ void zero_kernel() {
    int i = blockIdx.x * blockDim.x + threadIdx.x;
    if (i < N_NODES) { g_dis[i] = 0.f; g_cnt[i] = 0; }
}
__global__ void deg_hist_kernel(const void* __restrict__ ei, const float* __restrict__ ew) {
    int e = blockIdx.x * blockDim.x + threadIdx.x;
    if (e < N_EDGES) {
        unsigned r, c; load_edge(ei, e, r, c);
        if (r < N_NODES) atomicAdd(&g_dis[r], ew[e]);
        if (c < N_NODES) atomicAdd(&g_cnt[c], 1);
    }
}
__global__ void dis_kernel() {
    int i = blockIdx.x * blockDim.x + threadIdx.x;
    if (i < N_NODES) {
        float d = g_dis[i];
        g_dis[i] = (d > 0.f) ? rsqrtf(d) : 0.f;
    }
}
__global__ void scan1_kernel() {
    __shared__ int s[SCAN_BS];
    int t = threadIdx.x;
    int i = blockIdx.x * SCAN_BS + t;
    int v = (i < N_NODES) ? g_cnt[i] : 0;
    s[t] = v; __syncthreads();
    for (int d = 1; d < SCAN_BS; d <<= 1) {
        int add = (t >= d) ? s[t - d] : 0;
        __syncthreads(); s[t] += add; __syncthreads();
    }
    if (i < N_NODES) g_scan[i] = s[t];
    if (t == SCAN_BS - 1) g_bsum[blockIdx.x] = s[t];
}
__global__ void scan2_kernel() {
    __shared__ int s[128];
    int t = threadIdx.x;
    int v = (t < SCAN_NB) ? g_bsum[t] : 0;
    s[t] = v; __syncthreads();
    for (int d = 1; d < 128; d <<= 1) {
        int add = (t >= d) ? s[t - d] : 0;
        __syncthreads(); s[t] += add; __syncthreads();
    }
    if (t < SCAN_NB) g_boff[t] = s[t] - v;
}
__global__ void finalize_off_kernel() {
    int i = blockIdx.x * blockDim.x + threadIdx.x;
    if (i < N_NODES) {
        int incl = g_scan[i] + g_boff[i / SCAN_BS];
        int excl = incl - g_cnt[i];
        g_off[i] = excl; g_cur[i] = excl;
        if (i == N_NODES - 1) g_off[N_NODES] = incl;
    }
}
__global__ void fill_kernel(const void* __restrict__ ei, const float* __restrict__ ew) {
    int e = blockIdx.x * blockDim.x + threadIdx.x;
    if (e < N_EDGES) {
        unsigned r, c; load_edge(ei, e, r, c);
        if (r >= N_NODES || c >= N_NODES) return;
        float w = -g_dis[r] * ew[e] * g_dis[c];
        unsigned slot = (unsigned)atomicAdd(&g_cur[c], 1);
        if (slot >= N_EDGES) slot = N_EDGES - 1;
        g_pack[slot] = make_float2(__int_as_float((int)r), w);
    }
}
__global__ void __launch_bounds__(256)
prop_kernel(const float* __restrict__ x, int phase) {
    int gt = blockIdx.x * blockDim.x + threadIdx.x;
    int node = gt >> 5;
    int lane = gt & 31;
    if (node >= N_NODES) return;
    const float* src = (phase == 0) ? x : g_T1;
    float*       dst = (phase == 0) ? g_T1 : g_T2;
    int beg = g_off[node];
    int end = g_off[node + 1];
    if (beg < 0) beg = 0;
    if (end > N_EDGES) end = N_EDGES;
    const float2* s2 = reinterpret_cast<const float2*>(src);
    float ax = 0.f, ay = 0.f;
    int j = beg;
    for (; j + 2 <= end; j += 2) {
        float2 p0 = g_pack[j];
        float2 p1 = g_pack[j + 1];
        unsigned r0 = min((unsigned)__float_as_int(p0.x), N_NODES - 1u);
        unsigned r1 = min((unsigned)__float_as_int(p1.x), N_NODES - 1u);
        float2 v0 = s2[r0 * 32 + lane];
        float2 v1 = s2[r1 * 32 + lane];
        ax += p0.y * v0.x;  ay += p0.y * v0.y;
        ax += p1.y * v1.x;  ay += p1.y * v1.y;
    }
    if (j < end) {
        float2 p0 = g_pack[j];
        unsigned r0 = min((unsigned)__float_as_int(p0.x), N_NODES - 1u);
        float2 v0 = s2[r0 * 32 + lane];
        ax += p0.y * v0.x;  ay += p0.y * v0.y;
    }
    reinterpret_cast<float2*>(dst)[node * 32 + lane] = make_float2(ax, ay);
}

// WcT + bf16 hi/lo of WcT + bias
__global__ void prep_weights_kernel(
    const float* __restrict__ W10, const float* __restrict__ b1,
    const float* __restrict__ W20, const float* __restrict__ W21, const float* __restrict__ b2,
    const float* __restrict__ W30, const float* __restrict__ W31, const float* __restrict__ W32,
    const float* __restrict__ b3)
{
    int i = blockIdx.x * blockDim.x + threadIdx.x;
    if (i >= WC_ROWS * WC_COLS) return;
    int k = i / WC_COLS;
    int c = i % WC_COLS;
    float v = 0.f;
    if (k < 64) {
        if (c < 100)       v = W10[k * 100 + c];
        else if (c < 200)  v = W20[k * 100 + (c - 100)];
        else if (c < 300)  v = W30[k * 100 + (c - 200)] - W32[k * 100 + (c - 200)];
    } else if (k < 128) {
        int kk = k - 64;
        if (c >= 100 && c < 200)      v = W21[kk * 100 + (c - 100)];
        else if (c >= 200 && c < 300) v = W31[kk * 100 + (c - 200)];
    } else {
        int kk = k - 128;
        if (c >= 200 && c < 300) v = 2.f * W32[kk * 100 + (c - 200)];
    }
    g_WcT[c * WC_ROWS + k] = v;
    __nv_bfloat16 h = __float2bfloat16(v);
    __nv_bfloat16 l = __float2bfloat16(v - __bfloat162float(h));
    g_WTh[c * WC_ROWS + k] = h;
    g_WTl[c * WC_ROWS + k] = l;
    if (i < WC_COLS) {
        float bv = 0.f;
        if (i < 100)      bv = b1[i];
        else if (i < 200) bv = b2[i - 100];
        else if (i < 300) bv = b3[i - 200];
        g_bias[i] = bv;
    }
}

// convert A-tensor (phase 0:x, 1:T1, 2:T2) to bf16 hi/lo, zero-padding rows >= N_NODES
__global__ void convert_kernel(const float* __restrict__ x, int phase) {
    int idx = blockIdx.x * blockDim.x + threadIdx.x;     // row*16 + f4
    if (idx >= N_PAD * 16) return;
    int row = idx >> 4;
    int f4 = idx & 15;
    const float4* src = (phase == 0) ? reinterpret_cast<const float4*>(x)
                      : (phase == 1) ? reinterpret_cast<const float4*>(g_T1)
                                     : reinterpret_cast<const float4*>(g_T2);
    float4 v = make_float4(0.f, 0.f, 0.f, 0.f);
    if (row < N_NODES) v = src[row * 16 + f4];
    __nv_bfloat162 h01 = __floats2bfloat162_rn(v.x, v.y);
    __nv_bfloat162 h23 = __floats2bfloat162_rn(v.z, v.w);
    __nv_bfloat162 l01 = __floats2bfloat162_rn(v.x - __bfloat162float(__low2bfloat16(h01)),
                                               v.y - __bfloat162float(__high2bfloat16(h01)));
    __nv_bfloat162 l23 = __floats2bfloat162_rn(v.z - __bfloat162float(__low2bfloat16(h23)),
                                               v.w - __bfloat162float(__high2bfloat16(h23)));
    long long base = (long long)phase * N_PAD * D_IN + (long long)row * D_IN + f4 * 4;
    uint2 hv, lv;
    hv.x = *reinterpret_cast<uint32_t*>(&h01); hv.y = *reinterpret_cast<uint32_t*>(&h23);
    lv.x = *reinterpret_cast<uint32_t*>(&l01); lv.y = *reinterpret_cast<uint32_t*>(&l23);
    *reinterpret_cast<uint2*>(&g_Ah[base]) = hv;
    *reinterpret_cast<uint2*>(&g_Al[base]) = lv;
}

// ---------------- bf16 mma.sync GEMM, cp.async double-buffered ----------------
// Block 128 nodes x 64 cols, 8 warps (4x2), warp tile 32x32, 3-MMA split.
// smem: A bufs 2 x (hi+lo) x [128][72]b16 (144B pitch); B bufs 2 x (hi+lo) x [64][72]b16.
#define SA(buf, half) ((buf) * 36864 + (half) * 18432)
#define SB(buf, half) (73728 + (buf) * 18432 + (half) * 9216)
#define SM_GEMM 110592

__device__ __forceinline__ uint32_t smem_u32(const void* p) {
    uint32_t a;
    asm("{ .reg .u64 t; cvta.to.shared.u64 t, %1; cvt.u32.u64 %0, t; }" : "=r"(a) : "l"(p));
    return a;
}
__device__ __forceinline__ void cp16(uint32_t dst, const void* src) {
    asm volatile("cp.async.cg.shared.global [%0], [%1], 16;" :: "r"(dst), "l"(src));
}
__device__ __forceinline__ void cp_commit() {
    asm volatile("cp.async.commit_group;" ::: "memory");
}
template <int N>
__device__ __forceinline__ void cp_wait() {
    asm volatile("cp.async.wait_group %0;" :: "n"(N) : "memory");
}
__device__ __forceinline__ void ldm_x4(uint32_t& r0, uint32_t& r1, uint32_t& r2, uint32_t& r3, uint32_t a) {
    asm volatile("ldmatrix.sync.aligned.m8n8.x4.shared.b16 {%0,%1,%2,%3}, [%4];"
        : "=r"(r0), "=r"(r1), "=r"(r2), "=r"(r3) : "r"(a));
}
__device__ __forceinline__ void mma_bf16(float* d, const uint32_t* a, uint32_t b0, uint32_t b1) {
    asm volatile("mma.sync.aligned.m16n8k16.row.col.f32.bf16.bf16.f32 "
        "{%0,%1,%2,%3}, {%4,%5,%6,%7}, {%8,%9}, {%0,%1,%2,%3};"
        : "+f"(d[0]), "+f"(d[1]), "+f"(d[2]), "+f"(d[3])
        : "r"(a[0]), "r"(a[1]), "r"(a[2]), "r"(a[3]), "r"(b0), "r"(b1));
}

__global__ void __launch_bounds__(256, 2)
gemm_kernel(float* __restrict__ out)
{
    extern __shared__ __align__(16) char smem[];
    const uint32_t sb = smem_u32(smem);
    const int tid = threadIdx.x;
    const int wid = tid >> 5;
    const int lane = tid & 31;
    const int wr = wid & 3;
    const int wc = wid >> 2;
    const int tile = blockIdx.x;
    const int q = blockIdx.y;
    const int nch = (q == 0) ? 1 : (q < 3) ? 2 : 3;

    float acc[2][4][4];
#pragma unroll
    for (int mt = 0; mt < 2; mt++)
#pragma unroll
        for (int nt = 0; nt < 4; nt++)
#pragma unroll
            for (int i = 0; i < 4; i++) acc[mt][nt][i] = 0.f;

    // staging thread mapping
    const int aRow = tid >> 1;                    // 0..127 (2 chunks16/thread/iter covers row)
    // A: 128 rows x 8 x16B per half -> 1024 per half; per thread 4 (hi) + 4 (lo)
    // B: 64 rows x 8 x16B per half -> 512; per thread 2 + 2
    auto stage = [&](int c, int buf) {
        const __nv_bfloat16* ah = g_Ah + (long long)c * N_PAD * D_IN + (long long)tile * 128 * D_IN;
        const __nv_bfloat16* al = g_Al + (long long)c * N_PAD * D_IN + (long long)tile * 128 * D_IN;
#pragma unroll
        for (int i = 0; i < 4; i++) {
            int idx = tid + i * 256;              // 0..1023
            int row = idx >> 3, c16 = idx & 7;
            uint32_t doff = (uint32_t)(row * 144 + c16 * 16);
            cp16(sb + SA(buf, 0) + doff, (const char*)ah + row * 128 + c16 * 16);
            cp16(sb + SA(buf, 1) + doff, (const char*)al + row * 128 + c16 * 16);
        }
        const __nv_bfloat16* bh = g_WTh + (long long)(q * 64) * WC_ROWS + c * 64;
        const __nv_bfloat16* bl = g_WTl + (long long)(q * 64) * WC_ROWS + c * 64;
#pragma unroll
        for (int i = 0; i < 2; i++) {
            int idx = tid + i * 256;              // 0..511
            int row = idx >> 3, c16 = idx & 7;
            uint32_t doff = (uint32_t)(row * 144 + c16 * 16);
            cp16(sb + SB(buf, 0) + doff, (const char*)bh + row * 384 + c16 * 16);
            cp16(sb + SB(buf, 1) + doff, (const char*)bl + row * 384 + c16 * 16);
        }
        cp_commit();
    };

    const uint32_t aRowOff = (uint32_t)((wr * 32 + (lane & 15)) * 144 + (lane >> 4) * 16);
    const uint32_t bRowBase = (uint32_t)((wc * 32 + ((lane >> 4) << 3) + (lane & 7)) * 144
                                         + (((lane >> 3) & 1) ? 16 : 0));

    stage(0, 0);
    for (int c = 0; c < nch; c++) {
        int buf = c & 1;
        if (c + 1 < nch) stage(c + 1, buf ^ 1);
        if (c + 1 < nch) cp_wait<1>(); else cp_wait<0>();
        __syncthreads();

#pragma unroll
        for (int ks = 0; ks < 4; ks++) {
            uint32_t k0b = (uint32_t)(ks * 32);
            uint32_t ahi[2][4], alo[2][4];
#pragma unroll
            for (int mt = 0; mt < 2; mt++) {
                uint32_t aoff = aRowOff + (uint32_t)(mt * 16 * 144) + k0b;
                ldm_x4(ahi[mt][0], ahi[mt][1], ahi[mt][2], ahi[mt][3], sb + SA(buf, 0) + aoff);
                ldm_x4(alo[mt][0], alo[mt][1], alo[mt][2], alo[mt][3], sb + SA(buf, 1) + aoff);
            }
            uint32_t bhi[4][2], blo[4][2];
#pragma unroll
            for (int g2 = 0; g2 < 2; g2++) {
                uint32_t boff = bRowBase + (uint32_t)(g2 * 16 * 144) + k0b;
                ldm_x4(bhi[g2 * 2][0], bhi[g2 * 2][1], bhi[g2 * 2 + 1][0], bhi[g2 * 2 + 1][1],
                       sb + SB(buf, 0) + boff);
                ldm_x4(blo[g2 * 2][0], blo[g2 * 2][1], blo[g2 * 2 + 1][0], blo[g2 * 2 + 1][1],
                       sb + SB(buf, 1) + boff);
            }
#pragma unroll
            for (int mt = 0; mt < 2; mt++)
#pragma unroll
                for (int nt = 0; nt < 4; nt++) {
                    mma_bf16(acc[mt][nt], ahi[mt], bhi[nt][0], bhi[nt][1]);
                    mma_bf16(acc[mt][nt], ahi[mt], blo[nt][0], blo[nt][1]);
                    mma_bf16(acc[mt][nt], alo[mt], bhi[nt][0], bhi[nt][1]);
                }
        }
        __syncthreads();   // all warps done reading buf before it is restaged
    }

    // epilogue
    const int g = lane >> 2;
    const int c2 = (lane & 3) * 2;
#pragma unroll
    for (int mt = 0; mt < 2; mt++)
#pragma unroll
        for (int nt = 0; nt < 4; nt++) {
            int col = q * 64 + wc * 32 + nt * 8 + c2;
            if (col >= OUT_COLS) continue;
            float2 bv = *reinterpret_cast<const float2*>(&g_bias[col]);
#pragma unroll
            for (int h = 0; h < 2; h++) {
                int node = tile * 128 + wr * 32 + mt * 16 + g + h * 8;
                if (node < N_NODES) {
                    float2 o = make_float2(acc[mt][nt][h * 2 + 0] + bv.x,
                                           acc[mt][nt][h * 2 + 1] + bv.y);
                    *reinterpret_cast<float2*>(&out[(long long)node * OUT_COLS + col]) = o;
                }
            }
        }
}

// ---------------- launch ----------------
extern "C" void kernel_launch(void* const* d_in, const int* in_sizes, int n_in,
                              void* d_out, int out_size)
{
    const float* x = nullptr;
    const void*  ei = nullptr;
    const float* ew = nullptr;
    const float* Ws[6] = {};
    const float* Bs[3] = {};
    int nw = 0, nb = 0;
    for (int i = 0; i < n_in; i++) {
        int s = in_sizes[i];
        if (s == N_NODES * D_IN)      x = (const float*)d_in[i];
        else if (s == 2 * N_EDGES)    ei = d_in[i];
        else if (s == N_EDGES)        ew = (const float*)d_in[i];
        else if (s == D_IN * 100)     { if (nw < 6) Ws[nw++] = (const float*)d_in[i]; }
        else if (s == 100)            { if (nb < 3) Bs[nb++] = (const float*)d_in[i]; }
    }
    if (!x)  x  = (const float*)d_in[0];
    if (!ei) ei = d_in[1];
    if (!ew) ew = (const float*)d_in[2];
    if (nw < 6) {
        Ws[0] = (const float*)d_in[3];  Ws[1] = (const float*)d_in[5];
        Ws[2] = (const float*)d_in[6];  Ws[3] = (const float*)d_in[8];
        Ws[4] = (const float*)d_in[9];  Ws[5] = (const float*)d_in[10];
    }
    if (nb < 3) {
        Bs[0] = (const float*)d_in[4];  Bs[1] = (const float*)d_in[7];
        Bs[2] = (const float*)d_in[11];
    }
    float* out = (float*)d_out;

    cudaFuncSetAttribute(gemm_kernel, cudaFuncAttributeMaxDynamicSharedMemorySize, SM_GEMM);

    const int B = 256;
    const int nodeGrid = (N_NODES + B - 1) / B;
    const int edgeGrid = (N_EDGES + B - 1) / B;
    const int cvtGrid = (N_PAD * 16 + B - 1) / B;

    detect_dtype_kernel<<<1, 256>>>((const int*)ei);
    zero_kernel<<<nodeGrid, B>>>();
    deg_hist_kernel<<<edgeGrid, B>>>(ei, ew);
    dis_kernel<<<nodeGrid, B>>>();
    scan1_kernel<<<SCAN_NB, SCAN_BS>>>();
    scan2_kernel<<<1, 128>>>();
    finalize_off_kernel<<<nodeGrid, B>>>();
    fill_kernel<<<edgeGrid, B>>>(ei, ew);

    {
        long long items = (long long)N_NODES * 32;
        int grid = (int)((items + B - 1) / B);
        prop_kernel<<<grid, B>>>(x, 0);
        prop_kernel<<<grid, B>>>(x, 1);
    }

    convert_kernel<<<cvtGrid, B>>>(x, 0);
    convert_kernel<<<cvtGrid, B>>>(x, 1);
    convert_kernel<<<cvtGrid, B>>>(x, 2);

    prep_weights_kernel<<<(WC_ROWS * WC_COLS + B - 1) / B, B>>>(
        Ws[0], Bs[0], Ws[1], Ws[2], Bs[1], Ws[3], Ws[4], Ws[5], Bs[2]);

    {
        dim3 grid((N_NODES + 127) / 128, 5);
        gemm_kernel<<<grid, 256, SM_GEMM>>>(out);
    }
}

// round 13
// speedup vs baseline: 1.0512x; 1.0512x over previous
#include <cuda_runtime.h>
#include <cuda_bf16.h>
#include <cstdint>

#define N_NODES 100000
#define N_EDGES 1250000
#define D_IN    64
#define OUT_COLS 300
#define WC_COLS 320
#define WC_ROWS 192
#define SCAN_BS 1024
#define SCAN_NB ((N_NODES + SCAN_BS - 1) / SCAN_BS)   // 98
#define N_TILES 782

// ---------------- scratch (device globals) ----------------
__device__ __align__(16) float  g_dis[N_NODES];
__device__ __align__(16) int    g_cnt[N_NODES];
__device__ __align__(16) int    g_scan[N_NODES];
__device__ __align__(16) int    g_bsum[SCAN_NB];
__device__ __align__(16) int    g_boff[SCAN_NB];
__device__ __align__(16) int    g_off[N_NODES + 1];
__device__ __align__(16) int    g_cur[N_NODES];
__device__ __align__(16) float2 g_pack[N_EDGES];
__device__ __align__(16) float  g_T1[N_NODES * D_IN];
__device__ __align__(16) float  g_T2[N_NODES * D_IN];
__device__ __align__(16) __nv_bfloat16 g_WTh[WC_COLS * WC_ROWS];   // bf16 hi of WcT
__device__ __align__(16) __nv_bfloat16 g_WTl[WC_COLS * WC_ROWS];   // bf16 lo
__device__ __align__(16) float  g_bias[WC_COLS];
__device__ int g_is64;

// ---------------- edge dtype handling ----------------
__global__ void detect_dtype_kernel(const int* __restrict__ ei32) {
    __shared__ int nz;
    if (threadIdx.x == 0) nz = 0;
    __syncthreads();
    int w = 2 * threadIdx.x + 1;
    if (ei32[w] != 0) atomicAdd(&nz, 1);
    __syncthreads();
    if (threadIdx.x == 0) g_is64 = (nz == 0) ? 1 : 0;
}
__device__ __forceinline__ void load_edge(const void* ei, int e, unsigned& r, unsigned& c) {
    if (g_is64) {
        const long long* p = (const long long*)ei;
        r = (unsigned)(int)p[e];  c = (unsigned)(int)p[N_EDGES + e];
    } else {
        const int* p = (const int*)ei;
        r = (unsigned)p[e];       c = (unsigned)p[N_EDGES + e];
    }
}

// ---------------- graph pipeline (identical to passing R11) ----------------
__global__ void zero_kernel() {
    int i = blockIdx.x * blockDim.x + threadIdx.x;
    if (i < N_NODES) { g_dis[i] = 0.f; g_cnt[i] = 0; }
}
__global__ void deg_hist_kernel(const void* __restrict__ ei, const float* __restrict__ ew) {
    int e = blockIdx.x * blockDim.x + threadIdx.x;
    if (e < N_EDGES) {
        unsigned r, c; load_edge(ei, e, r, c);
        if (r < N_NODES) atomicAdd(&g_dis[r], ew[e]);
        if (c < N_NODES) atomicAdd(&g_cnt[c], 1);
    }
}
__global__ void dis_kernel() {
    int i = blockIdx.x * blockDim.x + threadIdx.x;
    if (i < N_NODES) {
        float d = g_dis[i];
        g_dis[i] = (d > 0.f) ? rsqrtf(d) : 0.f;
    }
}
__global__ void scan1_kernel() {
    __shared__ int s[SCAN_BS];
    int t = threadIdx.x;
    int i = blockIdx.x * SCAN_BS + t;
    int v = (i < N_NODES) ? g_cnt[i] : 0;
    s[t] = v; __syncthreads();
    for (int d = 1; d < SCAN_BS; d <<= 1) {
        int add = (t >= d) ? s[t - d] : 0;
        __syncthreads(); s[t] += add; __syncthreads();
    }
    if (i < N_NODES) g_scan[i] = s[t];
    if (t == SCAN_BS - 1) g_bsum[blockIdx.x] = s[t];
}
__global__ void scan2_kernel() {
    __shared__ int s[128];
    int t = threadIdx.x;
    int v = (t < SCAN_NB) ? g_bsum[t] : 0;
    s[t] = v; __syncthreads();
    for (int d = 1; d < 128; d <<= 1) {
        int add = (t >= d) ? s[t - d] : 0;
        __syncthreads(); s[t] += add; __syncthreads();
    }
    if (t < SCAN_NB) g_boff[t] = s[t] - v;
}
__global__ void finalize_off_kernel() {
    int i = blockIdx.x * blockDim.x + threadIdx.x;
    if (i < N_NODES) {
        int incl = g_scan[i] + g_boff[i / SCAN_BS];
        int excl = incl - g_cnt[i];
        g_off[i] = excl; g_cur[i] = excl;
        if (i == N_NODES - 1) g_off[N_NODES] = incl;
    }
}
__global__ void fill_kernel(const void* __restrict__ ei, const float* __restrict__ ew) {
    int e = blockIdx.x * blockDim.x + threadIdx.x;
    if (e < N_EDGES) {
        unsigned r, c; load_edge(ei, e, r, c);
        if (r >= N_NODES || c >= N_NODES) return;
        float w = -g_dis[r] * ew[e] * g_dis[c];
        unsigned slot = (unsigned)atomicAdd(&g_cur[c], 1);
        if (slot >= N_EDGES) slot = N_EDGES - 1;
        g_pack[slot] = make_float2(__int_as_float((int)r), w);
    }
}
__global__ void __launch_bounds__(256)
prop_kernel(const float* __restrict__ x, int phase) {
    int gt = blockIdx.x * blockDim.x + threadIdx.x;
    int node = gt >> 5;
    int lane = gt & 31;
    if (node >= N_NODES) return;
    const float* src = (phase == 0) ? x : g_T1;
    float*       dst = (phase == 0) ? g_T1 : g_T2;
    int beg = g_off[node];
    int end = g_off[node + 1];
    if (beg < 0) beg = 0;
    if (end > N_EDGES) end = N_EDGES;
    const float2* s2 = reinterpret_cast<const float2*>(src);
    float ax = 0.f, ay = 0.f;
    int j = beg;
    for (; j + 2 <= end; j += 2) {
        float2 p0 = g_pack[j];
        float2 p1 = g_pack[j + 1];
        unsigned r0 = min((unsigned)__float_as_int(p0.x), N_NODES - 1u);
        unsigned r1 = min((unsigned)__float_as_int(p1.x), N_NODES - 1u);
        float2 v0 = s2[r0 * 32 + lane];
        float2 v1 = s2[r1 * 32 + lane];
        ax += p0.y * v0.x;  ay += p0.y * v0.y;
        ax += p1.y * v1.x;  ay += p1.y * v1.y;
    }
    if (j < end) {
        float2 p0 = g_pack[j];
        unsigned r0 = min((unsigned)__float_as_int(p0.x), N_NODES - 1u);
        float2 v0 = s2[r0 * 32 + lane];
        ax += p0.y * v0.x;  ay += p0.y * v0.y;
    }
    reinterpret_cast<float2*>(dst)[node * 32 + lane] = make_float2(ax, ay);
}

// WcT bf16 hi/lo + bias (conversion folded in: free)
__global__ void prep_weights_kernel(
    const float* __restrict__ W10, const float* __restrict__ b1,
    const float* __restrict__ W20, const float* __restrict__ W21, const float* __restrict__ b2,
    const float* __restrict__ W30, const float* __restrict__ W31, const float* __restrict__ W32,
    const float* __restrict__ b3)
{
    int i = blockIdx.x * blockDim.x + threadIdx.x;
    if (i >= WC_ROWS * WC_COLS) return;
    int k = i / WC_COLS;
    int c = i % WC_COLS;
    float v = 0.f;
    if (k < 64) {
        if (c < 100)       v = W10[k * 100 + c];
        else if (c < 200)  v = W20[k * 100 + (c - 100)];
        else if (c < 300)  v = W30[k * 100 + (c - 200)] - W32[k * 100 + (c - 200)];
    } else if (k < 128) {
        int kk = k - 64;
        if (c >= 100 && c < 200)      v = W21[kk * 100 + (c - 100)];
        else if (c >= 200 && c < 300) v = W31[kk * 100 + (c - 200)];
    } else {
        int kk = k - 128;
        if (c >= 200 && c < 300) v = 2.f * W32[kk * 100 + (c - 200)];
    }
    __nv_bfloat16 h = __float2bfloat16(v);
    __nv_bfloat16 l = __float2bfloat16(v - __bfloat162float(h));
    g_WTh[c * WC_ROWS + k] = h;
    g_WTl[c * WC_ROWS + k] = l;
    if (i < WC_COLS) {
        float bv = 0.f;
        if (i < 100)      bv = b1[i];
        else if (i < 200) bv = b2[i - 100];
        else if (i < 300) bv = b3[i - 200];
        g_bias[i] = bv;
    }
}

// ---------------- bf16 mma.sync GEMM: A cached in smem across all quarters ----------------
// 1D grid over 782 node tiles. Block: 128 nodes, 8 warps (4 mrow x 2 ncol), warp tile 32x32.
// A: all 3 chunks (hi+lo) cached in smem, split in-kernel (hidden under staging).
// Quarters looped in-block; B chunks staged per quarter from pre-converted bf16 (no split).
// smem: A 3 x 2 x [128][72]b16 (144B pitch) = 110592; B 3 x 2 x [64][72]b16 = 55296. Total 165888.
#define SA(c, half) ((c) * 36864 + (half) * 18432)
#define SB(c, half) (110592 + (c) * 18432 + (half) * 9216)
#define SM_GEMM 165888

__device__ __forceinline__ uint32_t smem_u32(const void* p) {
    uint32_t a;
    asm("{ .reg .u64 t; cvta.to.shared.u64 t, %1; cvt.u32.u64 %0, t; }" : "=r"(a) : "l"(p));
    return a;
}
__device__ __forceinline__ void ldm_x4(uint32_t& r0, uint32_t& r1, uint32_t& r2, uint32_t& r3, uint32_t a) {
    asm volatile("ldmatrix.sync.aligned.m8n8.x4.shared.b16 {%0,%1,%2,%3}, [%4];"
        : "=r"(r0), "=r"(r1), "=r"(r2), "=r"(r3) : "r"(a));
}
__device__ __forceinline__ void mma_bf16(float* d, const uint32_t* a, uint32_t b0, uint32_t b1) {
    asm volatile("mma.sync.aligned.m16n8k16.row.col.f32.bf16.bf16.f32 "
        "{%0,%1,%2,%3}, {%4,%5,%6,%7}, {%8,%9}, {%0,%1,%2,%3};"
        : "+f"(d[0]), "+f"(d[1]), "+f"(d[2]), "+f"(d[3])
        : "r"(a[0]), "r"(a[1]), "r"(a[2]), "r"(a[3]), "r"(b0), "r"(b1));
}
__device__ __forceinline__ void split4(float4 v, uint2& hi, uint2& lo) {
    __nv_bfloat162 h01 = __floats2bfloat162_rn(v.x, v.y);
    __nv_bfloat162 h23 = __floats2bfloat162_rn(v.z, v.w);
    float lx = v.x - __bfloat162float(__low2bfloat16(h01));
    float ly = v.y - __bfloat162float(__high2bfloat16(h01));
    float lz = v.z - __bfloat162float(__low2bfloat16(h23));
    float lw = v.w - __bfloat162float(__high2bfloat16(h23));
    __nv_bfloat162 l01 = __floats2bfloat162_rn(lx, ly);
    __nv_bfloat162 l23 = __floats2bfloat162_rn(lz, lw);
    hi.x = *reinterpret_cast<uint32_t*>(&h01);
    hi.y = *reinterpret_cast<uint32_t*>(&h23);
    lo.x = *reinterpret_cast<uint32_t*>(&l01);
    lo.y = *reinterpret_cast<uint32_t*>(&l23);
}

__global__ void __launch_bounds__(256, 1)
gemm_kernel(const float* __restrict__ x, float* __restrict__ out)
{
    extern __shared__ __align__(16) char smem[];
    const uint32_t sb = smem_u32(smem);
    const int tid = threadIdx.x;
    const int wid = tid >> 5;
    const int lane = tid & 31;
    const int wr = wid & 3;
    const int wc = wid >> 2;
    const int tile = blockIdx.x;

    // ---- stage A: all 3 chunks (x, T1, T2), fp32 -> bf16 hi/lo split ----
#pragma unroll
    for (int c = 0; c < 3; c++) {
        const float4* s4 = (c == 0) ? reinterpret_cast<const float4*>(x)
                         : (c == 1) ? reinterpret_cast<const float4*>(g_T1)
                                    : reinterpret_cast<const float4*>(g_T2);
#pragma unroll
        for (int i = 0; i < 8; i++) {
            int idx = tid + i * 256;          // 0..2047
            int row = idx >> 4;               // 0..127
            int f4 = idx & 15;
            int node = tile * 128 + row;
            float4 v = make_float4(0.f, 0.f, 0.f, 0.f);
            if (node < N_NODES) v = s4[node * 16 + f4];
            uint2 hi, lo; split4(v, hi, lo);
            uint32_t off = (uint32_t)(row * 144 + f4 * 8);
            *reinterpret_cast<uint2*>(smem + SA(c, 0) + off) = hi;
            *reinterpret_cast<uint2*>(smem + SA(c, 1) + off) = lo;
        }
    }

    const uint32_t aRowOff = (uint32_t)((wr * 32 + (lane & 15)) * 144 + (lane >> 4) * 16);
    const uint32_t bRowBase = (uint32_t)((wc * 32 + ((lane >> 4) << 3) + (lane & 7)) * 144
                                         + (((lane >> 3) & 1) ? 16 : 0));
    const int g = lane >> 2;
    const int c2 = (lane & 3) * 2;

    for (int q = 0; q < 5; q++) {
        const int nch = (q == 0) ? 1 : (q < 3) ? 2 : 3;
        __syncthreads();   // previous quarter's compute done (q=0: A staging done)
        // ---- stage B chunks (bf16 direct copy, no split) ----
        for (int c = 0; c < nch; c++) {
            const char* bh = (const char*)g_WTh + (long long)(q * 64) * 384 + c * 128;
            const char* bl = (const char*)g_WTl + (long long)(q * 64) * 384 + c * 128;
#pragma unroll
            for (int i = 0; i < 2; i++) {
                int idx = tid + i * 256;      // 0..511
                int row = idx >> 3;           // 0..63
                int c16 = idx & 7;
                uint32_t doff = (uint32_t)(row * 144 + c16 * 16);
                *reinterpret_cast<uint4*>(smem + SB(c, 0) + doff) =
                    *reinterpret_cast<const uint4*>(bh + row * 384 + c16 * 16);
                *reinterpret_cast<uint4*>(smem + SB(c, 1) + doff) =
                    *reinterpret_cast<const uint4*>(bl + row * 384 + c16 * 16);
            }
        }
        __syncthreads();

        float acc[2][4][4];
#pragma unroll
        for (int mt = 0; mt < 2; mt++)
#pragma unroll
            for (int nt = 0; nt < 4; nt++)
#pragma unroll
                for (int i = 0; i < 4; i++) acc[mt][nt][i] = 0.f;

        for (int c = 0; c < nch; c++) {
#pragma unroll
            for (int ks = 0; ks < 4; ks++) {
                uint32_t k0b = (uint32_t)(ks * 32);
                uint32_t ahi[2][4], alo[2][4];
#pragma unroll
                for (int mt = 0; mt < 2; mt++) {
                    uint32_t aoff = aRowOff + (uint32_t)(mt * 16 * 144) + k0b;
                    ldm_x4(ahi[mt][0], ahi[mt][1], ahi[mt][2], ahi[mt][3], sb + SA(c, 0) + aoff);
                    ldm_x4(alo[mt][0], alo[mt][1], alo[mt][2], alo[mt][3], sb + SA(c, 1) + aoff);
                }
                uint32_t bhi[4][2], blo[4][2];
#pragma unroll
                for (int g2 = 0; g2 < 2; g2++) {
                    uint32_t boff = bRowBase + (uint32_t)(g2 * 16 * 144) + k0b;
                    ldm_x4(bhi[g2 * 2][0], bhi[g2 * 2][1], bhi[g2 * 2 + 1][0], bhi[g2 * 2 + 1][1],
                           sb + SB(c, 0) + boff);
                    ldm_x4(blo[g2 * 2][0], blo[g2 * 2][1], blo[g2 * 2 + 1][0], blo[g2 * 2 + 1][1],
                           sb + SB(c, 1) + boff);
                }
#pragma unroll
                for (int mt = 0; mt < 2; mt++)
#pragma unroll
                    for (int nt = 0; nt < 4; nt++) {
                        mma_bf16(acc[mt][nt], ahi[mt], bhi[nt][0], bhi[nt][1]);
                        mma_bf16(acc[mt][nt], ahi[mt], blo[nt][0], blo[nt][1]);
                        mma_bf16(acc[mt][nt], alo[mt], bhi[nt][0], bhi[nt][1]);
                    }
            }
        }

        // ---- epilogue for quarter q ----
#pragma unroll
        for (int mt = 0; mt < 2; mt++)
#pragma unroll
            for (int nt = 0; nt < 4; nt++) {
                int col = q * 64 + wc * 32 + nt * 8 + c2;
                if (col >= OUT_COLS) continue;
                float2 bv = *reinterpret_cast<const float2*>(&g_bias[col]);
#pragma unroll
                for (int h = 0; h < 2; h++) {
                    int node = tile * 128 + wr * 32 + mt * 16 + g + h * 8;
                    if (node < N_NODES) {
                        float2 o = make_float2(acc[mt][nt][h * 2 + 0] + bv.x,
                                               acc[mt][nt][h * 2 + 1] + bv.y);
                        *reinterpret_cast<float2*>(&out[(long long)node * OUT_COLS + col]) = o;
                    }
                }
            }
    }
}

// ---------------- launch ----------------
extern "C" void kernel_launch(void* const* d_in, const int* in_sizes, int n_in,
                              void* d_out, int out_size)
{
    const float* x = nullptr;
    const void*  ei = nullptr;
    const float* ew = nullptr;
    const float* Ws[6] = {};
    const float* Bs[3] = {};
    int nw = 0, nb = 0;
    for (int i = 0; i < n_in; i++) {
        int s = in_sizes[i];
        if (s == N_NODES * D_IN)      x = (const float*)d_in[i];
        else if (s == 2 * N_EDGES)    ei = d_in[i];
        else if (s == N_EDGES)        ew = (const float*)d_in[i];
        else if (s == D_IN * 100)     { if (nw < 6) Ws[nw++] = (const float*)d_in[i]; }
        else if (s == 100)            { if (nb < 3) Bs[nb++] = (const float*)d_in[i]; }
    }
    if (!x)  x  = (const float*)d_in[0];
    if (!ei) ei = d_in[1];
    if (!ew) ew = (const float*)d_in[2];
    if (nw < 6) {
        Ws[0] = (const float*)d_in[3];  Ws[1] = (const float*)d_in[5];
        Ws[2] = (const float*)d_in[6];  Ws[3] = (const float*)d_in[8];
        Ws[4] = (const float*)d_in[9];  Ws[5] = (const float*)d_in[10];
    }
    if (nb < 3) {
        Bs[0] = (const float*)d_in[4];  Bs[1] = (const float*)d_in[7];
        Bs[2] = (const float*)d_in[11];
    }
    float* out = (float*)d_out;

    cudaFuncSetAttribute(gemm_kernel, cudaFuncAttributeMaxDynamicSharedMemorySize, SM_GEMM);

    const int B = 256;
    const int nodeGrid = (N_NODES + B - 1) / B;
    const int edgeGrid = (N_EDGES + B - 1) / B;

    detect_dtype_kernel<<<1, 256>>>((const int*)ei);
    zero_kernel<<<nodeGrid, B>>>();
    deg_hist_kernel<<<edgeGrid, B>>>(ei, ew);
    dis_kernel<<<nodeGrid, B>>>();
    scan1_kernel<<<SCAN_NB, SCAN_BS>>>();
    scan2_kernel<<<1, 128>>>();
    finalize_off_kernel<<<nodeGrid, B>>>();
    fill_kernel<<<edgeGrid, B>>>(ei, ew);

    {
        long long items = (long long)N_NODES * 32;
        int grid = (int)((items + B - 1) / B);
        prop_kernel<<<grid, B>>>(x, 0);
        prop_kernel<<<grid, B>>>(x, 1);
    }

    prep_weights_kernel<<<(WC_ROWS * WC_COLS + B - 1) / B, B>>>(
        Ws[0], Bs[0], Ws[1], Ws[2], Bs[1], Ws[3], Ws[4], Ws[5], Bs[2]);

    {
        gemm_kernel<<<N_TILES, 256, SM_GEMM>>>(x, out);
    }
}

// round 14
// speedup vs baseline: 1.1553x; 1.0990x over previous
#include <cuda_runtime.h>
#include <cuda_fp16.h>
#include <cstdint>

#define N_NODES 100000
#define N_EDGES 1250000
#define D_IN    64
#define OUT_COLS 300
#define WC_COLS 320
#define WC_ROWS 192
#define SCAN_BS 1024
#define SCAN_NB ((N_NODES + SCAN_BS - 1) / SCAN_BS)   // 98

// ---------------- scratch (device globals) ----------------
__device__ __align__(16) float  g_dis[N_NODES];
__device__ __align__(16) int    g_cnt[N_NODES];
__device__ __align__(16) int    g_scan[N_NODES];
__device__ __align__(16) int    g_bsum[SCAN_NB];
__device__ __align__(16) int    g_boff[SCAN_NB];
__device__ __align__(16) int    g_off[N_NODES + 1];
__device__ __align__(16) int    g_cur[N_NODES];
__device__ __align__(16) float2 g_pack[N_EDGES];
__device__ __align__(16) float  g_T1[N_NODES * D_IN];
__device__ __align__(16) float  g_T2[N_NODES * D_IN];
__device__ __align__(16) float  g_WcT[WC_COLS * WC_ROWS];  // [col][k] fp32
__device__ __align__(16) float  g_bias[WC_COLS];
__device__ int g_is64;

// ---------------- edge dtype handling ----------------
__global__ void detect_dtype_kernel(const int* __restrict__ ei32) {
    __shared__ int nz;
    if (threadIdx.x == 0) nz = 0;
    __syncthreads();
    int w = 2 * threadIdx.x + 1;
    if (ei32[w] != 0) atomicAdd(&nz, 1);
    __syncthreads();
    if (threadIdx.x == 0) g_is64 = (nz == 0) ? 1 : 0;
}
__device__ __forceinline__ void load_edge(const void* ei, int e, unsigned& r, unsigned& c) {
    if (g_is64) {
        const long long* p = (const long long*)ei;
        r = (unsigned)(int)p[e];  c = (unsigned)(int)p[N_EDGES + e];
    } else {
        const int* p = (const int*)ei;
        r = (unsigned)p[e];       c = (unsigned)p[N_EDGES + e];
    }
}

// ---------------- graph pipeline (identical to passing R11) ----------------
__global__ void zero_kernel() {
    int i = blockIdx.x * blockDim.x + threadIdx.x;
    if (i < N_NODES) { g_dis[i] = 0.f; g_cnt[i] = 0; }
}
__global__ void deg_hist_kernel(const void* __restrict__ ei, const float* __restrict__ ew) {
    int e = blockIdx.x * blockDim.x + threadIdx.x;
    if (e < N_EDGES) {
        unsigned r, c; load_edge(ei, e, r, c);
        if (r < N_NODES) atomicAdd(&g_dis[r], ew[e]);
        if (c < N_NODES) atomicAdd(&g_cnt[c], 1);
    }
}
__global__ void dis_kernel() {
    int i = blockIdx.x * blockDim.x + threadIdx.x;
    if (i < N_NODES) {
        float d = g_dis[i];
        g_dis[i] = (d > 0.f) ? rsqrtf(d) : 0.f;
    }
}
__global__ void scan1_kernel() {
    __shared__ int s[SCAN_BS];
    int t = threadIdx.x;
    int i = blockIdx.x * SCAN_BS + t;
    int v = (i < N_NODES) ? g_cnt[i] : 0;
    s[t] = v; __syncthreads();
    for (int d = 1; d < SCAN_BS; d <<= 1) {
        int add = (t >= d) ? s[t - d] : 0;
        __syncthreads(); s[t] += add; __syncthreads();
    }
    if (i < N_NODES) g_scan[i] = s[t];
    if (t == SCAN_BS - 1) g_bsum[blockIdx.x] = s[t];
}
__global__ void scan2_kernel() {
    __shared__ int s[128];
    int t = threadIdx.x;
    int v = (t < SCAN_NB) ? g_bsum[t] : 0;
    s[t] = v; __syncthreads();
    for (int d = 1; d < 128; d <<= 1) {
        int add = (t >= d) ? s[t - d] : 0;
        __syncthreads(); s[t] += add; __syncthreads();
    }
    if (t < SCAN_NB) g_boff[t] = s[t] - v;
}
__global__ void finalize_off_kernel() {
    int i = blockIdx.x * blockDim.x + threadIdx.x;
    if (i < N_NODES) {
        int incl = g_scan[i] + g_boff[i / SCAN_BS];
        int excl = incl - g_cnt[i];
        g_off[i] = excl; g_cur[i] = excl;
        if (i == N_NODES - 1) g_off[N_NODES] = incl;
    }
}
__global__ void fill_kernel(const void* __restrict__ ei, const float* __restrict__ ew) {
    int e = blockIdx.x * blockDim.x + threadIdx.x;
    if (e < N_EDGES) {
        unsigned r, c; load_edge(ei, e, r, c);
        if (r >= N_NODES || c >= N_NODES) return;
        float w = -g_dis[r] * ew[e] * g_dis[c];
        unsigned slot = (unsigned)atomicAdd(&g_cur[c], 1);
        if (slot >= N_EDGES) slot = N_EDGES - 1;
        g_pack[slot] = make_float2(__int_as_float((int)r), w);
    }
}
__global__ void __launch_bounds__(256)
prop_kernel(const float* __restrict__ x, int phase) {
    int gt = blockIdx.x * blockDim.x + threadIdx.x;
    int node = gt >> 5;
    int lane = gt & 31;
    if (node >= N_NODES) return;
    const float* src = (phase == 0) ? x : g_T1;
    float*       dst = (phase == 0) ? g_T1 : g_T2;
    int beg = g_off[node];
    int end = g_off[node + 1];
    if (beg < 0) beg = 0;
    if (end > N_EDGES) end = N_EDGES;
    const float2* s2 = reinterpret_cast<const float2*>(src);
    float ax = 0.f, ay = 0.f;
    int j = beg;
    for (; j + 2 <= end; j += 2) {
        float2 p0 = g_pack[j];
        float2 p1 = g_pack[j + 1];
        unsigned r0 = min((unsigned)__float_as_int(p0.x), N_NODES - 1u);
        unsigned r1 = min((unsigned)__float_as_int(p1.x), N_NODES - 1u);
        float2 v0 = s2[r0 * 32 + lane];
        float2 v1 = s2[r1 * 32 + lane];
        ax += p0.y * v0.x;  ay += p0.y * v0.y;
        ax += p1.y * v1.x;  ay += p1.y * v1.y;
    }
    if (j < end) {
        float2 p0 = g_pack[j];
        unsigned r0 = min((unsigned)__float_as_int(p0.x), N_NODES - 1u);
        float2 v0 = s2[r0 * 32 + lane];
        ax += p0.y * v0.x;  ay += p0.y * v0.y;
    }
    reinterpret_cast<float2*>(dst)[node * 32 + lane] = make_float2(ax, ay);
}

// WcT[320][192] (transposed combined weights, fp32) + bias[320]
__global__ void prep_weights_kernel(
    const float* __restrict__ W10, const float* __restrict__ b1,
    const float* __restrict__ W20, const float* __restrict__ W21, const float* __restrict__ b2,
    const float* __restrict__ W30, const float* __restrict__ W31, const float* __restrict__ W32,
    const float* __restrict__ b3)
{
    int i = blockIdx.x * blockDim.x + threadIdx.x;
    if (i >= WC_ROWS * WC_COLS) return;
    int k = i / WC_COLS;
    int c = i % WC_COLS;
    float v = 0.f;
    if (k < 64) {
        if (c < 100)       v = W10[k * 100 + c];
        else if (c < 200)  v = W20[k * 100 + (c - 100)];
        else if (c < 300)  v = W30[k * 100 + (c - 200)] - W32[k * 100 + (c - 200)];
    } else if (k < 128) {
        int kk = k - 64;
        if (c >= 100 && c < 200)      v = W21[kk * 100 + (c - 100)];
        else if (c >= 200 && c < 300) v = W31[kk * 100 + (c - 200)];
    } else {
        int kk = k - 128;
        if (c >= 200 && c < 300) v = 2.f * W32[kk * 100 + (c - 200)];
    }
    g_WcT[c * WC_ROWS + k] = v;
    if (i < WC_COLS) {
        float bv = 0.f;
        if (i < 100)      bv = b1[i];
        else if (i < 200) bv = b2[i - 100];
        else if (i < 300) bv = b3[i - 200];
        g_bias[i] = bv;
    }
}

// ---------------- fp16 mma.sync GEMM (2-MMA split: A=hi+lo fp16, B=single fp16) ----------------
// out[100000,300] = [x|T1|T2p] @ Wc + bias.
// Block: 128 nodes x 64 cols, 8 warps (4 mrow x 2 ncol), warp tile 32x32.
// grid.y = col quarter (5 x 64); K chunks {1,2,2,3,3} of 64 (zero-block skipping).
// smem: Ahi[128][72]h, Alo[128][72]h, B[64][72]h ; 144B row pitch (ldmatrix conflict-free).
#define SA_HI 0
#define SA_LO 18432
#define SB_F  36864
#define SM_GEMM 46080

__device__ __forceinline__ uint32_t smem_u32(const void* p) {
    uint32_t a;
    asm("{ .reg .u64 t; cvta.to.shared.u64 t, %1; cvt.u32.u64 %0, t; }" : "=r"(a) : "l"(p));
    return a;
}
__device__ __forceinline__ void ldm_x4(uint32_t& r0, uint32_t& r1, uint32_t& r2, uint32_t& r3, uint32_t a) {
    asm volatile("ldmatrix.sync.aligned.m8n8.x4.shared.b16 {%0,%1,%2,%3}, [%4];"
        : "=r"(r0), "=r"(r1), "=r"(r2), "=r"(r3) : "r"(a));
}
__device__ __forceinline__ void mma_f16(float* d, const uint32_t* a, uint32_t b0, uint32_t b1) {
    asm volatile("mma.sync.aligned.m16n8k16.row.col.f32.f16.f16.f32 "
        "{%0,%1,%2,%3}, {%4,%5,%6,%7}, {%8,%9}, {%0,%1,%2,%3};"
        : "+f"(d[0]), "+f"(d[1]), "+f"(d[2]), "+f"(d[3])
        : "r"(a[0]), "r"(a[1]), "r"(a[2]), "r"(a[3]), "r"(b0), "r"(b1));
}
// fp32x4 -> fp16 hi + fp16 lo (hi+lo captures ~22 mantissa bits)
__device__ __forceinline__ void split4h(float4 v, uint2& hi, uint2& lo) {
    __half2 h01 = __floats2half2_rn(v.x, v.y);
    __half2 h23 = __floats2half2_rn(v.z, v.w);
    float lx = v.x - __half2float(__low2half(h01));
    float ly = v.y - __half2float(__high2half(h01));
    float lz = v.z - __half2float(__low2half(h23));
    float lw = v.w - __half2float(__high2half(h23));
    __half2 l01 = __floats2half2_rn(lx, ly);
    __half2 l23 = __floats2half2_rn(lz, lw);
    hi.x = *reinterpret_cast<uint32_t*>(&h01);
    hi.y = *reinterpret_cast<uint32_t*>(&h23);
    lo.x = *reinterpret_cast<uint32_t*>(&l01);
    lo.y = *reinterpret_cast<uint32_t*>(&l23);
}
__device__ __forceinline__ uint2 cvt4h(float4 v) {
    __half2 h01 = __floats2half2_rn(v.x, v.y);
    __half2 h23 = __floats2half2_rn(v.z, v.w);
    uint2 r;
    r.x = *reinterpret_cast<uint32_t*>(&h01);
    r.y = *reinterpret_cast<uint32_t*>(&h23);
    return r;
}

__global__ void __launch_bounds__(256, 2)
gemm_kernel(const float* __restrict__ x, float* __restrict__ out)
{
    extern __shared__ __align__(16) char smem[];
    const uint32_t sb = smem_u32(smem);
    const int tid = threadIdx.x;
    const int wid = tid >> 5;
    const int lane = tid & 31;
    const int wr = wid & 3;          // warp row (32 nodes)
    const int wc = wid >> 2;         // warp col (32 cols)
    const int tile = blockIdx.x;     // 128-node tile
    const int q = blockIdx.y;        // 64-col quarter
    const int nch = (q == 0) ? 1 : (q < 3) ? 2 : 3;

    float acc[2][4][4];
#pragma unroll
    for (int mt = 0; mt < 2; mt++)
#pragma unroll
        for (int nt = 0; nt < 4; nt++)
#pragma unroll
            for (int i = 0; i < 4; i++) acc[mt][nt][i] = 0.f;

    const uint32_t aRowOff = (uint32_t)((wr * 32 + (lane & 15)) * 144 + (lane >> 4) * 16);
    const uint32_t bRowBase = (uint32_t)((wc * 32 + ((lane >> 4) << 3) + (lane & 7)) * 144
                                         + (((lane >> 3) & 1) ? 16 : 0));

    for (int c = 0; c < nch; c++) {
        __syncthreads();
        // stage A: 128 rows x 64 k fp32 -> fp16 hi/lo
        const float4* s4 = (c == 0) ? reinterpret_cast<const float4*>(x)
                         : (c == 1) ? reinterpret_cast<const float4*>(g_T1)
                                    : reinterpret_cast<const float4*>(g_T2);
#pragma unroll
        for (int i = 0; i < 8; i++) {
            int idx = tid + i * 256;          // 0..2047
            int row = idx >> 4;               // 0..127
            int f4 = idx & 15;                // 0..15
            int node = tile * 128 + row;
            float4 v = make_float4(0.f, 0.f, 0.f, 0.f);
            if (node < N_NODES) v = s4[node * 16 + f4];
            uint2 hi, lo; split4h(v, hi, lo);
            uint32_t off = (uint32_t)(row * 144 + f4 * 8);
            *reinterpret_cast<uint2*>(smem + SA_HI + off) = hi;
            *reinterpret_cast<uint2*>(smem + SA_LO + off) = lo;
        }
        // stage B: 64 cols x 64 k fp32 from WcT -> single fp16
#pragma unroll
        for (int i = 0; i < 4; i++) {
            int idx = tid + i * 256;          // 0..1023
            int nrow = idx >> 4;              // 0..63
            int f4 = idx & 15;
            float4 v = *reinterpret_cast<const float4*>(
                &g_WcT[(q * 64 + nrow) * WC_ROWS + c * 64 + f4 * 4]);
            uint2 h = cvt4h(v);
            uint32_t off = (uint32_t)(nrow * 144 + f4 * 8);
            *reinterpret_cast<uint2*>(smem + SB_F + off) = h;
        }
        __syncthreads();

#pragma unroll
        for (int ks = 0; ks < 4; ks++) {
            uint32_t k0b = (uint32_t)(ks * 32);   // 16 k * 2B
            uint32_t ahi[2][4], alo[2][4];
#pragma unroll
            for (int mt = 0; mt < 2; mt++) {
                uint32_t aoff = aRowOff + (uint32_t)(mt * 16 * 144) + k0b;
                ldm_x4(ahi[mt][0], ahi[mt][1], ahi[mt][2], ahi[mt][3], sb + SA_HI + aoff);
                ldm_x4(alo[mt][0], alo[mt][1], alo[mt][2], alo[mt][3], sb + SA_LO + aoff);
            }
            uint32_t bf[4][2];
#pragma unroll
            for (int g2 = 0; g2 < 2; g2++) {      // each x4 covers 2 n-tiles
                uint32_t boff = bRowBase + (uint32_t)(g2 * 16 * 144) + k0b;
                ldm_x4(bf[g2 * 2][0], bf[g2 * 2][1], bf[g2 * 2 + 1][0], bf[g2 * 2 + 1][1],
                       sb + SB_F + boff);
            }
#pragma unroll
            for (int mt = 0; mt < 2; mt++)
#pragma unroll
                for (int nt = 0; nt < 4; nt++) {
                    mma_f16(acc[mt][nt], ahi[mt], bf[nt][0], bf[nt][1]);
                    mma_f16(acc[mt][nt], alo[mt], bf[nt][0], bf[nt][1]);
                }
        }
    }

    // epilogue: D frag thread t: rows g, g+8; cols 2*(t%4)+{0,1}
    const int g = lane >> 2;
    const int c2 = (lane & 3) * 2;
#pragma unroll
    for (int mt = 0; mt < 2; mt++)
#pragma unroll
        for (int nt = 0; nt < 4; nt++) {
            int col = q * 64 + wc * 32 + nt * 8 + c2;
            if (col >= OUT_COLS) continue;
            float2 bv = *reinterpret_cast<const float2*>(&g_bias[col]);
#pragma unroll
            for (int h = 0; h < 2; h++) {
                int node = tile * 128 + wr * 32 + mt * 16 + g + h * 8;
                if (node < N_NODES) {
                    float2 o = make_float2(acc[mt][nt][h * 2 + 0] + bv.x,
                                           acc[mt][nt][h * 2 + 1] + bv.y);
                    *reinterpret_cast<float2*>(&out[(long long)node * OUT_COLS + col]) = o;
                }
            }
        }
}

// ---------------- launch ----------------
extern "C" void kernel_launch(void* const* d_in, const int* in_sizes, int n_in,
                              void* d_out, int out_size)
{
    const float* x = nullptr;
    const void*  ei = nullptr;
    const float* ew = nullptr;
    const float* Ws[6] = {};
    const float* Bs[3] = {};
    int nw = 0, nb = 0;
    for (int i = 0; i < n_in; i++) {
        int s = in_sizes[i];
        if (s == N_NODES * D_IN)      x = (const float*)d_in[i];
        else if (s == 2 * N_EDGES)    ei = d_in[i];
        else if (s == N_EDGES)        ew = (const float*)d_in[i];
        else if (s == D_IN * 100)     { if (nw < 6) Ws[nw++] = (const float*)d_in[i]; }
        else if (s == 100)            { if (nb < 3) Bs[nb++] = (const float*)d_in[i]; }
    }
    if (!x)  x  = (const float*)d_in[0];
    if (!ei) ei = d_in[1];
    if (!ew) ew = (const float*)d_in[2];
    if (nw < 6) {
        Ws[0] = (const float*)d_in[3];  Ws[1] = (const float*)d_in[5];
        Ws[2] = (const float*)d_in[6];  Ws[3] = (const float*)d_in[8];
        Ws[4] = (const float*)d_in[9];  Ws[5] = (const float*)d_in[10];
    }
    if (nb < 3) {
        Bs[0] = (const float*)d_in[4];  Bs[1] = (const float*)d_in[7];
        Bs[2] = (const float*)d_in[11];
    }
    float* out = (float*)d_out;

    cudaFuncSetAttribute(gemm_kernel, cudaFuncAttributeMaxDynamicSharedMemorySize, SM_GEMM);

    const int B = 256;
    const int nodeGrid = (N_NODES + B - 1) / B;
    const int edgeGrid = (N_EDGES + B - 1) / B;

    detect_dtype_kernel<<<1, 256>>>((const int*)ei);
    zero_kernel<<<nodeGrid, B>>>();
    deg_hist_kernel<<<edgeGrid, B>>>(ei, ew);
    dis_kernel<<<nodeGrid, B>>>();
    scan1_kernel<<<SCAN_NB, SCAN_BS>>>();
    scan2_kernel<<<1, 128>>>();
    finalize_off_kernel<<<nodeGrid, B>>>();
    fill_kernel<<<edgeGrid, B>>>(ei, ew);

    {
        long long items = (long long)N_NODES * 32;
        int grid = (int)((items + B - 1) / B);
        prop_kernel<<<grid, B>>>(x, 0);
        prop_kernel<<<grid, B>>>(x, 1);
    }

    prep_weights_kernel<<<(WC_ROWS * WC_COLS + B - 1) / B, B>>>(
        Ws[0], Bs[0], Ws[1], Ws[2], Bs[1], Ws[3], Ws[4], Ws[5], Bs[2]);

    {
        dim3 grid((N_NODES + 127) / 128, 5);
        gemm_kernel<<<grid, 256, SM_GEMM>>>(x, out);
    }
}

// round 15
// speedup vs baseline: 1.1783x; 1.0200x over previous
#include <cuda_runtime.h>
#include <cuda_fp16.h>
#include <cstdint>

#define N_NODES 100000
#define N_EDGES 1250000
#define D_IN    64
#define OUT_COLS 300
#define WC_COLS 320
#define WC_ROWS 192
#define SCAN_BS 1024
#define SCAN_NB ((N_NODES + SCAN_BS - 1) / SCAN_BS)   // 98

// ---------------- scratch (device globals) ----------------
__device__ __align__(16) float  g_dis[N_NODES];
__device__ __align__(16) int    g_cnt[N_NODES];
__device__ __align__(16) int    g_scan[N_NODES];
__device__ __align__(16) int    g_bsum[SCAN_NB];
__device__ __align__(16) int    g_boff[SCAN_NB];
__device__ __align__(16) int    g_off[N_NODES + 1];
__device__ __align__(16) int    g_cur[N_NODES];
__device__ __align__(16) float2 g_pack[N_EDGES];
__device__ __align__(16) float  g_T1[N_NODES * D_IN];
__device__ __align__(16) float  g_T2[N_NODES * D_IN];
__device__ __align__(16) float  g_WcT[WC_COLS * WC_ROWS];  // [col][k] fp32
__device__ __align__(16) float  g_bias[WC_COLS];
__device__ int g_is64;

// ---------------- edge dtype handling ----------------
__global__ void detect_dtype_kernel(const int* __restrict__ ei32) {
    __shared__ int nz;
    if (threadIdx.x == 0) nz = 0;
    __syncthreads();
    int w = 2 * threadIdx.x + 1;
    if (ei32[w] != 0) atomicAdd(&nz, 1);
    __syncthreads();
    if (threadIdx.x == 0) g_is64 = (nz == 0) ? 1 : 0;
}
__device__ __forceinline__ void load_edge(const void* ei, int e, unsigned& r, unsigned& c) {
    if (g_is64) {
        const long long* p = (const long long*)ei;
        r = (unsigned)(int)p[e];  c = (unsigned)(int)p[N_EDGES + e];
    } else {
        const int* p = (const int*)ei;
        r = (unsigned)p[e];       c = (unsigned)p[N_EDGES + e];
    }
}

// ---------------- graph pipeline (identical to passing R14) ----------------
__global__ void zero_kernel() {
    int i = blockIdx.x * blockDim.x + threadIdx.x;
    if (i < N_NODES) { g_dis[i] = 0.f; g_cnt[i] = 0; }
}
__global__ void deg_hist_kernel(const void* __restrict__ ei, const float* __restrict__ ew) {
    int e = blockIdx.x * blockDim.x + threadIdx.x;
    if (e < N_EDGES) {
        unsigned r, c; load_edge(ei, e, r, c);
        if (r < N_NODES) atomicAdd(&g_dis[r], ew[e]);
        if (c < N_NODES) atomicAdd(&g_cnt[c], 1);
    }
}
__global__ void dis_kernel() {
    int i = blockIdx.x * blockDim.x + threadIdx.x;
    if (i < N_NODES) {
        float d = g_dis[i];
        g_dis[i] = (d > 0.f) ? rsqrtf(d) : 0.f;
    }
}
__global__ void scan1_kernel() {
    __shared__ int s[SCAN_BS];
    int t = threadIdx.x;
    int i = blockIdx.x * SCAN_BS + t;
    int v = (i < N_NODES) ? g_cnt[i] : 0;
    s[t] = v; __syncthreads();
    for (int d = 1; d < SCAN_BS; d <<= 1) {
        int add = (t >= d) ? s[t - d] : 0;
        __syncthreads(); s[t] += add; __syncthreads();
    }
    if (i < N_NODES) g_scan[i] = s[t];
    if (t == SCAN_BS - 1) g_bsum[blockIdx.x] = s[t];
}
__global__ void scan2_kernel() {
    __shared__ int s[128];
    int t = threadIdx.x;
    int v = (t < SCAN_NB) ? g_bsum[t] : 0;
    s[t] = v; __syncthreads();
    for (int d = 1; d < 128; d <<= 1) {
        int add = (t >= d) ? s[t - d] : 0;
        __syncthreads(); s[t] += add; __syncthreads();
    }
    if (t < SCAN_NB) g_boff[t] = s[t] - v;
}
__global__ void finalize_off_kernel() {
    int i = blockIdx.x * blockDim.x + threadIdx.x;
    if (i < N_NODES) {
        int incl = g_scan[i] + g_boff[i / SCAN_BS];
        int excl = incl - g_cnt[i];
        g_off[i] = excl; g_cur[i] = excl;
        if (i == N_NODES - 1) g_off[N_NODES] = incl;
    }
}
__global__ void fill_kernel(const void* __restrict__ ei, const float* __restrict__ ew) {
    int e = blockIdx.x * blockDim.x + threadIdx.x;
    if (e < N_EDGES) {
        unsigned r, c; load_edge(ei, e, r, c);
        if (r >= N_NODES || c >= N_NODES) return;
        float w = -g_dis[r] * ew[e] * g_dis[c];
        unsigned slot = (unsigned)atomicAdd(&g_cur[c], 1);
        if (slot >= N_EDGES) slot = N_EDGES - 1;
        g_pack[slot] = make_float2(__int_as_float((int)r), w);
    }
}
__global__ void __launch_bounds__(256)
prop_kernel(const float* __restrict__ x, int phase) {
    int gt = blockIdx.x * blockDim.x + threadIdx.x;
    int node = gt >> 5;
    int lane = gt & 31;
    if (node >= N_NODES) return;
    const float* src = (phase == 0) ? x : g_T1;
    float*       dst = (phase == 0) ? g_T1 : g_T2;
    int beg = g_off[node];
    int end = g_off[node + 1];
    if (beg < 0) beg = 0;
    if (end > N_EDGES) end = N_EDGES;
    const float2* s2 = reinterpret_cast<const float2*>(src);
    float ax = 0.f, ay = 0.f;
    int j = beg;
    for (; j + 2 <= end; j += 2) {
        float2 p0 = g_pack[j];
        float2 p1 = g_pack[j + 1];
        unsigned r0 = min((unsigned)__float_as_int(p0.x), N_NODES - 1u);
        unsigned r1 = min((unsigned)__float_as_int(p1.x), N_NODES - 1u);
        float2 v0 = s2[r0 * 32 + lane];
        float2 v1 = s2[r1 * 32 + lane];
        ax += p0.y * v0.x;  ay += p0.y * v0.y;
        ax += p1.y * v1.x;  ay += p1.y * v1.y;
    }
    if (j < end) {
        float2 p0 = g_pack[j];
        unsigned r0 = min((unsigned)__float_as_int(p0.x), N_NODES - 1u);
        float2 v0 = s2[r0 * 32 + lane];
        ax += p0.y * v0.x;  ay += p0.y * v0.y;
    }
    reinterpret_cast<float2*>(dst)[node * 32 + lane] = make_float2(ax, ay);
}

// WcT[320][192] (transposed combined weights, fp32) + bias[320]
__global__ void prep_weights_kernel(
    const float* __restrict__ W10, const float* __restrict__ b1,
    const float* __restrict__ W20, const float* __restrict__ W21, const float* __restrict__ b2,
    const float* __restrict__ W30, const float* __restrict__ W31, const float* __restrict__ W32,
    const float* __restrict__ b3)
{
    int i = blockIdx.x * blockDim.x + threadIdx.x;
    if (i >= WC_ROWS * WC_COLS) return;
    int k = i / WC_COLS;
    int c = i % WC_COLS;
    float v = 0.f;
    if (k < 64) {
        if (c < 100)       v = W10[k * 100 + c];
        else if (c < 200)  v = W20[k * 100 + (c - 100)];
        else if (c < 300)  v = W30[k * 100 + (c - 200)] - W32[k * 100 + (c - 200)];
    } else if (k < 128) {
        int kk = k - 64;
        if (c >= 100 && c < 200)      v = W21[kk * 100 + (c - 100)];
        else if (c >= 200 && c < 300) v = W31[kk * 100 + (c - 200)];
    } else {
        int kk = k - 128;
        if (c >= 200 && c < 300) v = 2.f * W32[kk * 100 + (c - 200)];
    }
    g_WcT[c * WC_ROWS + k] = v;
    if (i < WC_COLS) {
        float bv = 0.f;
        if (i < 100)      bv = b1[i];
        else if (i < 200) bv = b2[i - 100];
        else if (i < 300) bv = b3[i - 200];
        g_bias[i] = bv;
    }
}

// ---------------- fp16 mma.sync GEMM (2-MMA split), q passed via q_base + blockIdx.y ----------------
#define SA_HI 0
#define SA_LO 18432
#define SB_F  36864
#define SM_GEMM 46080

__device__ __forceinline__ uint32_t smem_u32(const void* p) {
    uint32_t a;
    asm("{ .reg .u64 t; cvta.to.shared.u64 t, %1; cvt.u32.u64 %0, t; }" : "=r"(a) : "l"(p));
    return a;
}
__device__ __forceinline__ void ldm_x4(uint32_t& r0, uint32_t& r1, uint32_t& r2, uint32_t& r3, uint32_t a) {
    asm volatile("ldmatrix.sync.aligned.m8n8.x4.shared.b16 {%0,%1,%2,%3}, [%4];"
        : "=r"(r0), "=r"(r1), "=r"(r2), "=r"(r3) : "r"(a));
}
__device__ __forceinline__ void mma_f16(float* d, const uint32_t* a, uint32_t b0, uint32_t b1) {
    asm volatile("mma.sync.aligned.m16n8k16.row.col.f32.f16.f16.f32 "
        "{%0,%1,%2,%3}, {%4,%5,%6,%7}, {%8,%9}, {%0,%1,%2,%3};"
        : "+f"(d[0]), "+f"(d[1]), "+f"(d[2]), "+f"(d[3])
        : "r"(a[0]), "r"(a[1]), "r"(a[2]), "r"(a[3]), "r"(b0), "r"(b1));
}
__device__ __forceinline__ void split4h(float4 v, uint2& hi, uint2& lo) {
    __half2 h01 = __floats2half2_rn(v.x, v.y);
    __half2 h23 = __floats2half2_rn(v.z, v.w);
    float lx = v.x - __half2float(__low2half(h01));
    float ly = v.y - __half2float(__high2half(h01));
    float lz = v.z - __half2float(__low2half(h23));
    float lw = v.w - __half2float(__high2half(h23));
    __half2 l01 = __floats2half2_rn(lx, ly);
    __half2 l23 = __floats2half2_rn(lz, lw);
    hi.x = *reinterpret_cast<uint32_t*>(&h01);
    hi.y = *reinterpret_cast<uint32_t*>(&h23);
    lo.x = *reinterpret_cast<uint32_t*>(&l01);
    lo.y = *reinterpret_cast<uint32_t*>(&l23);
}
__device__ __forceinline__ uint2 cvt4h(float4 v) {
    __half2 h01 = __floats2half2_rn(v.x, v.y);
    __half2 h23 = __floats2half2_rn(v.z, v.w);
    uint2 r;
    r.x = *reinterpret_cast<uint32_t*>(&h01);
    r.y = *reinterpret_cast<uint32_t*>(&h23);
    return r;
}

__global__ void __launch_bounds__(256, 2)
gemm_kernel(const float* __restrict__ x, float* __restrict__ out, int q_base)
{
    extern __shared__ __align__(16) char smem[];
    const uint32_t sb = smem_u32(smem);
    const int tid = threadIdx.x;
    const int wid = tid >> 5;
    const int lane = tid & 31;
    const int wr = wid & 3;
    const int wc = wid >> 2;
    const int tile = blockIdx.x;
    const int q = q_base + blockIdx.y;
    const int nch = (q == 0) ? 1 : (q < 3) ? 2 : 3;

    float acc[2][4][4];
#pragma unroll
    for (int mt = 0; mt < 2; mt++)
#pragma unroll
        for (int nt = 0; nt < 4; nt++)
#pragma unroll
            for (int i = 0; i < 4; i++) acc[mt][nt][i] = 0.f;

    const uint32_t aRowOff = (uint32_t)((wr * 32 + (lane & 15)) * 144 + (lane >> 4) * 16);
    const uint32_t bRowBase = (uint32_t)((wc * 32 + ((lane >> 4) << 3) + (lane & 7)) * 144
                                         + (((lane >> 3) & 1) ? 16 : 0));

    for (int c = 0; c < nch; c++) {
        __syncthreads();
        const float4* s4 = (c == 0) ? reinterpret_cast<const float4*>(x)
                         : (c == 1) ? reinterpret_cast<const float4*>(g_T1)
                                    : reinterpret_cast<const float4*>(g_T2);
#pragma unroll
        for (int i = 0; i < 8; i++) {
            int idx = tid + i * 256;
            int row = idx >> 4;
            int f4 = idx & 15;
            int node = tile * 128 + row;
            float4 v = make_float4(0.f, 0.f, 0.f, 0.f);
            if (node < N_NODES) v = s4[node * 16 + f4];
            uint2 hi, lo; split4h(v, hi, lo);
            uint32_t off = (uint32_t)(row * 144 + f4 * 8);
            *reinterpret_cast<uint2*>(smem + SA_HI + off) = hi;
            *reinterpret_cast<uint2*>(smem + SA_LO + off) = lo;
        }
#pragma unroll
        for (int i = 0; i < 4; i++) {
            int idx = tid + i * 256;
            int nrow = idx >> 4;
            int f4 = idx & 15;
            float4 v = *reinterpret_cast<const float4*>(
                &g_WcT[(q * 64 + nrow) * WC_ROWS + c * 64 + f4 * 4]);
            uint2 h = cvt4h(v);
            uint32_t off = (uint32_t)(nrow * 144 + f4 * 8);
            *reinterpret_cast<uint2*>(smem + SB_F + off) = h;
        }
        __syncthreads();

#pragma unroll
        for (int ks = 0; ks < 4; ks++) {
            uint32_t k0b = (uint32_t)(ks * 32);
            uint32_t ahi[2][4], alo[2][4];
#pragma unroll
            for (int mt = 0; mt < 2; mt++) {
                uint32_t aoff = aRowOff + (uint32_t)(mt * 16 * 144) + k0b;
                ldm_x4(ahi[mt][0], ahi[mt][1], ahi[mt][2], ahi[mt][3], sb + SA_HI + aoff);
                ldm_x4(alo[mt][0], alo[mt][1], alo[mt][2], alo[mt][3], sb + SA_LO + aoff);
            }
            uint32_t bf[4][2];
#pragma unroll
            for (int g2 = 0; g2 < 2; g2++) {
                uint32_t boff = bRowBase + (uint32_t)(g2 * 16 * 144) + k0b;
                ldm_x4(bf[g2 * 2][0], bf[g2 * 2][1], bf[g2 * 2 + 1][0], bf[g2 * 2 + 1][1],
                       sb + SB_F + boff);
            }
#pragma unroll
            for (int mt = 0; mt < 2; mt++)
#pragma unroll
                for (int nt = 0; nt < 4; nt++) {
                    mma_f16(acc[mt][nt], ahi[mt], bf[nt][0], bf[nt][1]);
                    mma_f16(acc[mt][nt], alo[mt], bf[nt][0], bf[nt][1]);
                }
        }
    }

    const int g = lane >> 2;
    const int c2 = (lane & 3) * 2;
#pragma unroll
    for (int mt = 0; mt < 2; mt++)
#pragma unroll
        for (int nt = 0; nt < 4; nt++) {
            int col = q * 64 + wc * 32 + nt * 8 + c2;
            if (col >= OUT_COLS) continue;
            float2 bv = *reinterpret_cast<const float2*>(&g_bias[col]);
#pragma unroll
            for (int h = 0; h < 2; h++) {
                int node = tile * 128 + wr * 32 + mt * 16 + g + h * 8;
                if (node < N_NODES) {
                    float2 o = make_float2(acc[mt][nt][h * 2 + 0] + bv.x,
                                           acc[mt][nt][h * 2 + 1] + bv.y);
                    *reinterpret_cast<float2*>(&out[(long long)node * OUT_COLS + col]) = o;
                }
            }
        }
}

// ---------------- launch (multi-stream fork/join, capture-legal) ----------------
extern "C" void kernel_launch(void* const* d_in, const int* in_sizes, int n_in,
                              void* d_out, int out_size)
{
    const float* x = nullptr;
    const void*  ei = nullptr;
    const float* ew = nullptr;
    const float* Ws[6] = {};
    const float* Bs[3] = {};
    int nw = 0, nb = 0;
    for (int i = 0; i < n_in; i++) {
        int s = in_sizes[i];
        if (s == N_NODES * D_IN)      x = (const float*)d_in[i];
        else if (s == 2 * N_EDGES)    ei = d_in[i];
        else if (s == N_EDGES)        ew = (const float*)d_in[i];
        else if (s == D_IN * 100)     { if (nw < 6) Ws[nw++] = (const float*)d_in[i]; }
        else if (s == 100)            { if (nb < 3) Bs[nb++] = (const float*)d_in[i]; }
    }
    if (!x)  x  = (const float*)d_in[0];
    if (!ei) ei = d_in[1];
    if (!ew) ew = (const float*)d_in[2];
    if (nw < 6) {
        Ws[0] = (const float*)d_in[3];  Ws[1] = (const float*)d_in[5];
        Ws[2] = (const float*)d_in[6];  Ws[3] = (const float*)d_in[8];
        Ws[4] = (const float*)d_in[9];  Ws[5] = (const float*)d_in[10];
    }
    if (nb < 3) {
        Bs[0] = (const float*)d_in[4];  Bs[1] = (const float*)d_in[7];
        Bs[2] = (const float*)d_in[11];
    }
    float* out = (float*)d_out;

    cudaFuncSetAttribute(gemm_kernel, cudaFuncAttributeMaxDynamicSharedMemorySize, SM_GEMM);

    const int B = 256;
    const int nodeGrid = (N_NODES + B - 1) / B;
    const int edgeGrid = (N_EDGES + B - 1) / B;
    const int tileGrid = (N_NODES + 127) / 128;

    // side stream + events (host-side resources; few calls total, leak is benign)
    cudaStream_t s2;
    cudaStreamCreate(&s2);
    cudaEvent_t evFork, evW, evP0, evJoin;
    cudaEventCreateWithFlags(&evFork, cudaEventDisableTiming);
    cudaEventCreateWithFlags(&evW,    cudaEventDisableTiming);
    cudaEventCreateWithFlags(&evP0,   cudaEventDisableTiming);
    cudaEventCreateWithFlags(&evJoin, cudaEventDisableTiming);

    // ---- main chain (default stream): CSR + props + GEMM q3,q4 ----
    detect_dtype_kernel<<<1, 256>>>((const int*)ei);
    cudaEventRecord(evFork, 0);                      // fork point for side stream

    // ---- side stream: prep_weights -> GEMM q0 (x only) -> after prop0: GEMM q1,q2 ----
    cudaStreamWaitEvent(s2, evFork, 0);
    prep_weights_kernel<<<(WC_ROWS * WC_COLS + B - 1) / B, B, 0, s2>>>(
        Ws[0], Bs[0], Ws[1], Ws[2], Bs[1], Ws[3], Ws[4], Ws[5], Bs[2]);
    cudaEventRecord(evW, s2);
    {
        dim3 grid(tileGrid, 1);
        gemm_kernel<<<grid, 256, SM_GEMM, s2>>>(x, out, 0);       // q0: needs x only
    }

    // ---- main chain continues ----
    zero_kernel<<<nodeGrid, B>>>();
    deg_hist_kernel<<<edgeGrid, B>>>(ei, ew);
    dis_kernel<<<nodeGrid, B>>>();
    scan1_kernel<<<SCAN_NB, SCAN_BS>>>();
    scan2_kernel<<<1, 128>>>();
    finalize_off_kernel<<<nodeGrid, B>>>();
    fill_kernel<<<edgeGrid, B>>>(ei, ew);
    {
        long long items = (long long)N_NODES * 32;
        int grid = (int)((items + B - 1) / B);
        prop_kernel<<<grid, B>>>(x, 0);              // T1
        cudaEventRecord(evP0, 0);
        prop_kernel<<<grid, B>>>(x, 1);              // T2
    }

    // side: q1,q2 need T1 (prop0) + weights
    cudaStreamWaitEvent(s2, evP0, 0);
    {
        dim3 grid(tileGrid, 2);
        gemm_kernel<<<grid, 256, SM_GEMM, s2>>>(x, out, 1);       // q1,q2
    }
    cudaEventRecord(evJoin, s2);

    // main: q3,q4 need T2 + weights
    cudaStreamWaitEvent(0, evW, 0);
    {
        dim3 grid(tileGrid, 2);
        gemm_kernel<<<grid, 256, SM_GEMM>>>(x, out, 3);           // q3,q4
    }
    cudaStreamWaitEvent(0, evJoin, 0);               // join side stream before return
}

// round 16
// speedup vs baseline: 1.2457x; 1.0572x over previous
#include <cuda_runtime.h>
#include <cuda_fp16.h>
#include <cstdint>

#define N_NODES 100000
#define N_EDGES 1250000
#define D_IN    64
#define OUT_COLS 300
#define WC_COLS 320
#define WC_ROWS 192
#define SCAN_BS 1024
#define SCAN_NB ((N_NODES + SCAN_BS - 1) / SCAN_BS)   // 98

// ---------------- scratch (device globals) ----------------
__device__ __align__(16) float  g_dis[N_NODES];
__device__ __align__(16) int    g_cnt[N_NODES];
__device__ __align__(16) int    g_scan[N_NODES];
__device__ __align__(16) int    g_bsum[SCAN_NB];
__device__ __align__(16) int    g_boff[SCAN_NB];
__device__ __align__(16) int    g_off[N_NODES + 1];
__device__ __align__(16) int    g_cur[N_NODES];
__device__ __align__(16) float2 g_pack[N_EDGES];
__device__ __align__(16) float  g_T1[N_NODES * D_IN];
__device__ __align__(16) float  g_T2[N_NODES * D_IN];
__device__ __align__(16) float  g_WcT[WC_COLS * WC_ROWS];  // [col][k] fp32
__device__ __align__(16) float  g_bias[WC_COLS];
__device__ int g_is64;

// ---------------- edge dtype handling ----------------
__global__ void detect_dtype_kernel(const int* __restrict__ ei32) {
    __shared__ int nz;
    if (threadIdx.x == 0) nz = 0;
    __syncthreads();
    int w = 2 * threadIdx.x + 1;
    if (ei32[w] != 0) atomicAdd(&nz, 1);
    __syncthreads();
    if (threadIdx.x == 0) g_is64 = (nz == 0) ? 1 : 0;
}
__device__ __forceinline__ void load_edge(const void* ei, int e, unsigned& r, unsigned& c) {
    if (g_is64) {
        const long long* p = (const long long*)ei;
        r = (unsigned)(int)p[e];  c = (unsigned)(int)p[N_EDGES + e];
    } else {
        const int* p = (const int*)ei;
        r = (unsigned)p[e];       c = (unsigned)p[N_EDGES + e];
    }
}

// ---------------- graph pipeline (identical to passing R15) ----------------
__global__ void zero_kernel() {
    int i = blockIdx.x * blockDim.x + threadIdx.x;
    if (i < N_NODES) { g_dis[i] = 0.f; g_cnt[i] = 0; }
}
__global__ void deg_hist_kernel(const void* __restrict__ ei, const float* __restrict__ ew) {
    int e = blockIdx.x * blockDim.x + threadIdx.x;
    if (e < N_EDGES) {
        unsigned r, c; load_edge(ei, e, r, c);
        if (r < N_NODES) atomicAdd(&g_dis[r], ew[e]);
        if (c < N_NODES) atomicAdd(&g_cnt[c], 1);
    }
}
__global__ void dis_kernel() {
    int i = blockIdx.x * blockDim.x + threadIdx.x;
    if (i < N_NODES) {
        float d = g_dis[i];
        g_dis[i] = (d > 0.f) ? rsqrtf(d) : 0.f;
    }
}
__global__ void scan1_kernel() {
    __shared__ int s[SCAN_BS];
    int t = threadIdx.x;
    int i = blockIdx.x * SCAN_BS + t;
    int v = (i < N_NODES) ? g_cnt[i] : 0;
    s[t] = v; __syncthreads();
    for (int d = 1; d < SCAN_BS; d <<= 1) {
        int add = (t >= d) ? s[t - d] : 0;
        __syncthreads(); s[t] += add; __syncthreads();
    }
    if (i < N_NODES) g_scan[i] = s[t];
    if (t == SCAN_BS - 1) g_bsum[blockIdx.x] = s[t];
}
__global__ void scan2_kernel() {
    __shared__ int s[128];
    int t = threadIdx.x;
    int v = (t < SCAN_NB) ? g_bsum[t] : 0;
    s[t] = v; __syncthreads();
    for (int d = 1; d < 128; d <<= 1) {
        int add = (t >= d) ? s[t - d] : 0;
        __syncthreads(); s[t] += add; __syncthreads();
    }
    if (t < SCAN_NB) g_boff[t] = s[t] - v;
}
__global__ void finalize_off_kernel() {
    int i = blockIdx.x * blockDim.x + threadIdx.x;
    if (i < N_NODES) {
        int incl = g_scan[i] + g_boff[i / SCAN_BS];
        int excl = incl - g_cnt[i];
        g_off[i] = excl; g_cur[i] = excl;
        if (i == N_NODES - 1) g_off[N_NODES] = incl;
    }
}
__global__ void fill_kernel(const void* __restrict__ ei, const float* __restrict__ ew) {
    int e = blockIdx.x * blockDim.x + threadIdx.x;
    if (e < N_EDGES) {
        unsigned r, c; load_edge(ei, e, r, c);
        if (r >= N_NODES || c >= N_NODES) return;
        float w = -g_dis[r] * ew[e] * g_dis[c];
        unsigned slot = (unsigned)atomicAdd(&g_cur[c], 1);
        if (slot >= N_EDGES) slot = N_EDGES - 1;
        g_pack[slot] = make_float2(__int_as_float((int)r), w);
    }
}
__global__ void __launch_bounds__(256)
prop_kernel(const float* __restrict__ x, int phase) {
    int gt = blockIdx.x * blockDim.x + threadIdx.x;
    int node = gt >> 5;
    int lane = gt & 31;
    if (node >= N_NODES) return;
    const float* src = (phase == 0) ? x : g_T1;
    float*       dst = (phase == 0) ? g_T1 : g_T2;
    int beg = g_off[node];
    int end = g_off[node + 1];
    if (beg < 0) beg = 0;
    if (end > N_EDGES) end = N_EDGES;
    const float2* s2 = reinterpret_cast<const float2*>(src);
    float ax = 0.f, ay = 0.f;
    int j = beg;
    for (; j + 2 <= end; j += 2) {
        float2 p0 = g_pack[j];
        float2 p1 = g_pack[j + 1];
        unsigned r0 = min((unsigned)__float_as_int(p0.x), N_NODES - 1u);
        unsigned r1 = min((unsigned)__float_as_int(p1.x), N_NODES - 1u);
        float2 v0 = s2[r0 * 32 + lane];
        float2 v1 = s2[r1 * 32 + lane];
        ax += p0.y * v0.x;  ay += p0.y * v0.y;
        ax += p1.y * v1.x;  ay += p1.y * v1.y;
    }
    if (j < end) {
        float2 p0 = g_pack[j];
        unsigned r0 = min((unsigned)__float_as_int(p0.x), N_NODES - 1u);
        float2 v0 = s2[r0 * 32 + lane];
        ax += p0.y * v0.x;  ay += p0.y * v0.y;
    }
    reinterpret_cast<float2*>(dst)[node * 32 + lane] = make_float2(ax, ay);
}

// WcT[320][192] (transposed combined weights, fp32) + bias[320]
__global__ void prep_weights_kernel(
    const float* __restrict__ W10, const float* __restrict__ b1,
    const float* __restrict__ W20, const float* __restrict__ W21, const float* __restrict__ b2,
    const float* __restrict__ W30, const float* __restrict__ W31, const float* __restrict__ W32,
    const float* __restrict__ b3)
{
    int i = blockIdx.x * blockDim.x + threadIdx.x;
    if (i >= WC_ROWS * WC_COLS) return;
    int k = i / WC_COLS;
    int c = i % WC_COLS;
    float v = 0.f;
    if (k < 64) {
        if (c < 100)       v = W10[k * 100 + c];
        else if (c < 200)  v = W20[k * 100 + (c - 100)];
        else if (c < 300)  v = W30[k * 100 + (c - 200)] - W32[k * 100 + (c - 200)];
    } else if (k < 128) {
        int kk = k - 64;
        if (c >= 100 && c < 200)      v = W21[kk * 100 + (c - 100)];
        else if (c >= 200 && c < 300) v = W31[kk * 100 + (c - 200)];
    } else {
        int kk = k - 128;
        if (c >= 200 && c < 300) v = 2.f * W32[kk * 100 + (c - 200)];
    }
    g_WcT[c * WC_ROWS + k] = v;
    if (i < WC_COLS) {
        float bv = 0.f;
        if (i < 100)      bv = b1[i];
        else if (i < 200) bv = b2[i - 100];
        else if (i < 300) bv = b3[i - 200];
        g_bias[i] = bv;
    }
}

// ---------------- fp16 mma.sync GEMM (single MMA: A fp16, B fp16) ----------------
// out[100000,300] = [x|T1|T2p] @ Wc + bias.
// Block: 128 nodes x 64 cols, 8 warps (4 mrow x 2 ncol), warp tile 32x32.
// grid.y = col quarter (q_base + blockIdx.y); K chunks {1,2,2,3,3} of 64.
// smem: A[128][72]h, B[64][72]h ; 144B row pitch (ldmatrix conflict-free).
#define SA_F 0
#define SB_F 18432
#define SM_GEMM 27648

__device__ __forceinline__ uint32_t smem_u32(const void* p) {
    uint32_t a;
    asm("{ .reg .u64 t; cvta.to.shared.u64 t, %1; cvt.u32.u64 %0, t; }" : "=r"(a) : "l"(p));
    return a;
}
__device__ __forceinline__ void ldm_x4(uint32_t& r0, uint32_t& r1, uint32_t& r2, uint32_t& r3, uint32_t a) {
    asm volatile("ldmatrix.sync.aligned.m8n8.x4.shared.b16 {%0,%1,%2,%3}, [%4];"
        : "=r"(r0), "=r"(r1), "=r"(r2), "=r"(r3) : "r"(a));
}
__device__ __forceinline__ void mma_f16(float* d, const uint32_t* a, uint32_t b0, uint32_t b1) {
    asm volatile("mma.sync.aligned.m16n8k16.row.col.f32.f16.f16.f32 "
        "{%0,%1,%2,%3}, {%4,%5,%6,%7}, {%8,%9}, {%0,%1,%2,%3};"
        : "+f"(d[0]), "+f"(d[1]), "+f"(d[2]), "+f"(d[3])
        : "r"(a[0]), "r"(a[1]), "r"(a[2]), "r"(a[3]), "r"(b0), "r"(b1));
}
__device__ __forceinline__ uint2 cvt4h(float4 v) {
    __half2 h01 = __floats2half2_rn(v.x, v.y);
    __half2 h23 = __floats2half2_rn(v.z, v.w);
    uint2 r;
    r.x = *reinterpret_cast<uint32_t*>(&h01);
    r.y = *reinterpret_cast<uint32_t*>(&h23);
    return r;
}

__global__ void __launch_bounds__(256, 2)
gemm_kernel(const float* __restrict__ x, float* __restrict__ out, int q_base)
{
    extern __shared__ __align__(16) char smem[];
    const uint32_t sb = smem_u32(smem);
    const int tid = threadIdx.x;
    const int wid = tid >> 5;
    const int lane = tid & 31;
    const int wr = wid & 3;
    const int wc = wid >> 2;
    const int tile = blockIdx.x;
    const int q = q_base + blockIdx.y;
    const int nch = (q == 0) ? 1 : (q < 3) ? 2 : 3;

    float acc[2][4][4];
#pragma unroll
    for (int mt = 0; mt < 2; mt++)
#pragma unroll
        for (int nt = 0; nt < 4; nt++)
#pragma unroll
            for (int i = 0; i < 4; i++) acc[mt][nt][i] = 0.f;

    const uint32_t aRowOff = (uint32_t)((wr * 32 + (lane & 15)) * 144 + (lane >> 4) * 16);
    const uint32_t bRowBase = (uint32_t)((wc * 32 + ((lane >> 4) << 3) + (lane & 7)) * 144
                                         + (((lane >> 3) & 1) ? 16 : 0));

    for (int c = 0; c < nch; c++) {
        __syncthreads();
        // stage A: 128 rows x 64 k fp32 -> fp16
        const float4* s4 = (c == 0) ? reinterpret_cast<const float4*>(x)
                         : (c == 1) ? reinterpret_cast<const float4*>(g_T1)
                                    : reinterpret_cast<const float4*>(g_T2);
#pragma unroll
        for (int i = 0; i < 8; i++) {
            int idx = tid + i * 256;          // 0..2047
            int row = idx >> 4;               // 0..127
            int f4 = idx & 15;
            int node = tile * 128 + row;
            float4 v = make_float4(0.f, 0.f, 0.f, 0.f);
            if (node < N_NODES) v = s4[node * 16 + f4];
            uint2 h = cvt4h(v);
            uint32_t off = (uint32_t)(row * 144 + f4 * 8);
            *reinterpret_cast<uint2*>(smem + SA_F + off) = h;
        }
        // stage B: 64 cols x 64 k fp32 -> fp16
#pragma unroll
        for (int i = 0; i < 4; i++) {
            int idx = tid + i * 256;          // 0..1023
            int nrow = idx >> 4;              // 0..63
            int f4 = idx & 15;
            float4 v = *reinterpret_cast<const float4*>(
                &g_WcT[(q * 64 + nrow) * WC_ROWS + c * 64 + f4 * 4]);
            uint2 h = cvt4h(v);
            uint32_t off = (uint32_t)(nrow * 144 + f4 * 8);
            *reinterpret_cast<uint2*>(smem + SB_F + off) = h;
        }
        __syncthreads();

#pragma unroll
        for (int ks = 0; ks < 4; ks++) {
            uint32_t k0b = (uint32_t)(ks * 32);   // 16 k * 2B
            uint32_t af[2][4];
#pragma unroll
            for (int mt = 0; mt < 2; mt++) {
                uint32_t aoff = aRowOff + (uint32_t)(mt * 16 * 144) + k0b;
                ldm_x4(af[mt][0], af[mt][1], af[mt][2], af[mt][3], sb + SA_F + aoff);
            }
            uint32_t bf[4][2];
#pragma unroll
            for (int g2 = 0; g2 < 2; g2++) {
                uint32_t boff = bRowBase + (uint32_t)(g2 * 16 * 144) + k0b;
                ldm_x4(bf[g2 * 2][0], bf[g2 * 2][1], bf[g2 * 2 + 1][0], bf[g2 * 2 + 1][1],
                       sb + SB_F + boff);
            }
#pragma unroll
            for (int mt = 0; mt < 2; mt++)
#pragma unroll
                for (int nt = 0; nt < 4; nt++)
                    mma_f16(acc[mt][nt], af[mt], bf[nt][0], bf[nt][1]);
        }
    }

    const int g = lane >> 2;
    const int c2 = (lane & 3) * 2;
#pragma unroll
    for (int mt = 0; mt < 2; mt++)
#pragma unroll
        for (int nt = 0; nt < 4; nt++) {
            int col = q * 64 + wc * 32 + nt * 8 + c2;
            if (col >= OUT_COLS) continue;
            float2 bv = *reinterpret_cast<const float2*>(&g_bias[col]);
#pragma unroll
            for (int h = 0; h < 2; h++) {
                int node = tile * 128 + wr * 32 + mt * 16 + g + h * 8;
                if (node < N_NODES) {
                    float2 o = make_float2(acc[mt][nt][h * 2 + 0] + bv.x,
                                           acc[mt][nt][h * 2 + 1] + bv.y);
                    *reinterpret_cast<float2*>(&out[(long long)node * OUT_COLS + col]) = o;
                }
            }
        }
}

// ---------------- launch (multi-stream fork/join, capture-legal) ----------------
extern "C" void kernel_launch(void* const* d_in, const int* in_sizes, int n_in,
                              void* d_out, int out_size)
{
    const float* x = nullptr;
    const void*  ei = nullptr;
    const float* ew = nullptr;
    const float* Ws[6] = {};
    const float* Bs[3] = {};
    int nw = 0, nb = 0;
    for (int i = 0; i < n_in; i++) {
        int s = in_sizes[i];
        if (s == N_NODES * D_IN)      x = (const float*)d_in[i];
        else if (s == 2 * N_EDGES)    ei = d_in[i];
        else if (s == N_EDGES)        ew = (const float*)d_in[i];
        else if (s == D_IN * 100)     { if (nw < 6) Ws[nw++] = (const float*)d_in[i]; }
        else if (s == 100)            { if (nb < 3) Bs[nb++] = (const float*)d_in[i]; }
    }
    if (!x)  x  = (const float*)d_in[0];
    if (!ei) ei = d_in[1];
    if (!ew) ew = (const float*)d_in[2];
    if (nw < 6) {
        Ws[0] = (const float*)d_in[3];  Ws[1] = (const float*)d_in[5];
        Ws[2] = (const float*)d_in[6];  Ws[3] = (const float*)d_in[8];
        Ws[4] = (const float*)d_in[9];  Ws[5] = (const float*)d_in[10];
    }
    if (nb < 3) {
        Bs[0] = (const float*)d_in[4];  Bs[1] = (const float*)d_in[7];
        Bs[2] = (const float*)d_in[11];
    }
    float* out = (float*)d_out;

    cudaFuncSetAttribute(gemm_kernel, cudaFuncAttributeMaxDynamicSharedMemorySize, SM_GEMM);

    const int B = 256;
    const int nodeGrid = (N_NODES + B - 1) / B;
    const int edgeGrid = (N_EDGES + B - 1) / B;
    const int tileGrid = (N_NODES + 127) / 128;

    cudaStream_t s2;
    cudaStreamCreate(&s2);
    cudaEvent_t evFork, evW, evP0, evJoin;
    cudaEventCreateWithFlags(&evFork, cudaEventDisableTiming);
    cudaEventCreateWithFlags(&evW,    cudaEventDisableTiming);
    cudaEventCreateWithFlags(&evP0,   cudaEventDisableTiming);
    cudaEventCreateWithFlags(&evJoin, cudaEventDisableTiming);

    // ---- main chain: CSR + props + GEMM q3,q4 ----
    detect_dtype_kernel<<<1, 256>>>((const int*)ei);
    cudaEventRecord(evFork, 0);

    // ---- side stream: prep_weights -> GEMM q0 -> (after prop0) GEMM q1,q2 ----
    cudaStreamWaitEvent(s2, evFork, 0);
    prep_weights_kernel<<<(WC_ROWS * WC_COLS + B - 1) / B, B, 0, s2>>>(
        Ws[0], Bs[0], Ws[1], Ws[2], Bs[1], Ws[3], Ws[4], Ws[5], Bs[2]);
    cudaEventRecord(evW, s2);
    {
        dim3 grid(tileGrid, 1);
        gemm_kernel<<<grid, 256, SM_GEMM, s2>>>(x, out, 0);
    }

    zero_kernel<<<nodeGrid, B>>>();
    deg_hist_kernel<<<edgeGrid, B>>>(ei, ew);
    dis_kernel<<<nodeGrid, B>>>();
    scan1_kernel<<<SCAN_NB, SCAN_BS>>>();
    scan2_kernel<<<1, 128>>>();
    finalize_off_kernel<<<nodeGrid, B>>>();
    fill_kernel<<<edgeGrid, B>>>(ei, ew);
    {
        long long items = (long long)N_NODES * 32;
        int grid = (int)((items + B - 1) / B);
        prop_kernel<<<grid, B>>>(x, 0);
        cudaEventRecord(evP0, 0);
        prop_kernel<<<grid, B>>>(x, 1);
    }

    cudaStreamWaitEvent(s2, evP0, 0);
    {
        dim3 grid(tileGrid, 2);
        gemm_kernel<<<grid, 256, SM_GEMM, s2>>>(x, out, 1);
    }
    cudaEventRecord(evJoin, s2);

    cudaStreamWaitEvent(0, evW, 0);
    {
        dim3 grid(tileGrid, 2);
        gemm_kernel<<<grid, 256, SM_GEMM>>>(x, out, 3);
    }
    cudaStreamWaitEvent(0, evJoin, 0);
}

// round 17
// speedup vs baseline: 1.3031x; 1.0460x over previous
#include <cuda_runtime.h>
#include <cuda_fp16.h>
#include <cstdint>

#define N_NODES 100000
#define N_EDGES 1250000
#define D_IN    64
#define OUT_COLS 300
#define WC_COLS 320
#define WC_ROWS 192
#define SCAN_BS 1024
#define SCAN_NB ((N_NODES + SCAN_BS - 1) / SCAN_BS)   // 98

// ---------------- scratch (device globals) ----------------
__device__ __align__(16) float  g_dis[N_NODES];
__device__ __align__(16) int    g_cnt[N_NODES];
__device__ __align__(16) int    g_scan[N_NODES];
__device__ __align__(16) int    g_bsum[SCAN_NB];
__device__ __align__(16) int    g_boff[SCAN_NB];
__device__ __align__(16) int    g_off[N_NODES + 1];
__device__ __align__(16) int    g_cur[N_NODES];
__device__ __align__(16) float2 g_pack[N_EDGES];
__device__ __align__(16) __half g_xh[N_NODES * D_IN];   // fp16 x
__device__ __align__(16) __half g_T1h[N_NODES * D_IN];  // fp16 T1
__device__ __align__(16) __half g_T2h[N_NODES * D_IN];  // fp16 T2p
__device__ __align__(16) float  g_WcT[WC_COLS * WC_ROWS];  // [col][k] fp32
__device__ __align__(16) float  g_bias[WC_COLS];
__device__ int g_is64;

// ---------------- edge dtype handling ----------------
__global__ void detect_dtype_kernel(const int* __restrict__ ei32) {
    __shared__ int nz;
    if (threadIdx.x == 0) nz = 0;
    __syncthreads();
    int w = 2 * threadIdx.x + 1;
    if (ei32[w] != 0) atomicAdd(&nz, 1);
    __syncthreads();
    if (threadIdx.x == 0) g_is64 = (nz == 0) ? 1 : 0;
}
__device__ __forceinline__ void load_edge(const void* ei, int e, unsigned& r, unsigned& c) {
    if (g_is64) {
        const long long* p = (const long long*)ei;
        r = (unsigned)(int)p[e];  c = (unsigned)(int)p[N_EDGES + e];
    } else {
        const int* p = (const int*)ei;
        r = (unsigned)p[e];       c = (unsigned)p[N_EDGES + e];
    }
}

// ---------------- graph pipeline ----------------
__global__ void zero_kernel() {
    int i = blockIdx.x * blockDim.x + threadIdx.x;
    if (i < N_NODES) { g_dis[i] = 0.f; g_cnt[i] = 0; }
}
__global__ void deg_hist_kernel(const void* __restrict__ ei, const float* __restrict__ ew) {
    int e = blockIdx.x * blockDim.x + threadIdx.x;
    if (e < N_EDGES) {
        unsigned r, c; load_edge(ei, e, r, c);
        if (r < N_NODES) atomicAdd(&g_dis[r], ew[e]);
        if (c < N_NODES) atomicAdd(&g_cnt[c], 1);
    }
}
__global__ void dis_kernel() {
    int i = blockIdx.x * blockDim.x + threadIdx.x;
    if (i < N_NODES) {
        float d = g_dis[i];
        g_dis[i] = (d > 0.f) ? rsqrtf(d) : 0.f;
    }
}
__global__ void scan1_kernel() {
    __shared__ int s[SCAN_BS];
    int t = threadIdx.x;
    int i = blockIdx.x * SCAN_BS + t;
    int v = (i < N_NODES) ? g_cnt[i] : 0;
    s[t] = v; __syncthreads();
    for (int d = 1; d < SCAN_BS; d <<= 1) {
        int add = (t >= d) ? s[t - d] : 0;
        __syncthreads(); s[t] += add; __syncthreads();
    }
    if (i < N_NODES) g_scan[i] = s[t];
    if (t == SCAN_BS - 1) g_bsum[blockIdx.x] = s[t];
}
__global__ void scan2_kernel() {
    __shared__ int s[128];
    int t = threadIdx.x;
    int v = (t < SCAN_NB) ? g_bsum[t] : 0;
    s[t] = v; __syncthreads();
    for (int d = 1; d < 128; d <<= 1) {
        int add = (t >= d) ? s[t - d] : 0;
        __syncthreads(); s[t] += add; __syncthreads();
    }
    if (t < SCAN_NB) g_boff[t] = s[t] - v;
}
__global__ void finalize_off_kernel() {
    int i = blockIdx.x * blockDim.x + threadIdx.x;
    if (i < N_NODES) {
        int incl = g_scan[i] + g_boff[i / SCAN_BS];
        int excl = incl - g_cnt[i];
        g_off[i] = excl; g_cur[i] = excl;
        if (i == N_NODES - 1) g_off[N_NODES] = incl;
    }
}
__global__ void fill_kernel(const void* __restrict__ ei, const float* __restrict__ ew) {
    int e = blockIdx.x * blockDim.x + threadIdx.x;
    if (e < N_EDGES) {
        unsigned r, c; load_edge(ei, e, r, c);
        if (r >= N_NODES || c >= N_NODES) return;
        float w = -g_dis[r] * ew[e] * g_dis[c];
        unsigned slot = (unsigned)atomicAdd(&g_cur[c], 1);
        if (slot >= N_EDGES) slot = N_EDGES - 1;
        g_pack[slot] = make_float2(__int_as_float((int)r), w);
    }
}

// convert x (fp32) -> g_xh (fp16)
__global__ void convert_x_kernel(const float* __restrict__ x) {
    int i = blockIdx.x * blockDim.x + threadIdx.x;   // over N_NODES*32 half2
    if (i < N_NODES * 32) {
        float2 v = reinterpret_cast<const float2*>(x)[i];
        reinterpret_cast<__half2*>(g_xh)[i] = __floats2half2_rn(v.x, v.y);
    }
}

// gather prop on fp16 storage: one warp per node, lane owns one half2 (2 features).
// fp32 accumulate; fp16 store. phase 0: xh -> T1h ; 1: T1h -> T2h.
__global__ void __launch_bounds__(256)
prop_kernel(int phase) {
    int gt = blockIdx.x * blockDim.x + threadIdx.x;
    int node = gt >> 5;
    int lane = gt & 31;
    if (node >= N_NODES) return;
    const __half2* src = (phase == 0) ? reinterpret_cast<const __half2*>(g_xh)
                                      : reinterpret_cast<const __half2*>(g_T1h);
    __half2* dst = (phase == 0) ? reinterpret_cast<__half2*>(g_T1h)
                                : reinterpret_cast<__half2*>(g_T2h);
    int beg = g_off[node];
    int end = g_off[node + 1];
    if (beg < 0) beg = 0;
    if (end > N_EDGES) end = N_EDGES;
    float ax = 0.f, ay = 0.f;
    int j = beg;
    for (; j + 2 <= end; j += 2) {
        float2 p0 = g_pack[j];
        float2 p1 = g_pack[j + 1];
        unsigned r0 = min((unsigned)__float_as_int(p0.x), N_NODES - 1u);
        unsigned r1 = min((unsigned)__float_as_int(p1.x), N_NODES - 1u);
        float2 v0 = __half22float2(src[r0 * 32 + lane]);
        float2 v1 = __half22float2(src[r1 * 32 + lane]);
        ax += p0.y * v0.x;  ay += p0.y * v0.y;
        ax += p1.y * v1.x;  ay += p1.y * v1.y;
    }
    if (j < end) {
        float2 p0 = g_pack[j];
        unsigned r0 = min((unsigned)__float_as_int(p0.x), N_NODES - 1u);
        float2 v0 = __half22float2(src[r0 * 32 + lane]);
        ax += p0.y * v0.x;  ay += p0.y * v0.y;
    }
    dst[node * 32 + lane] = __floats2half2_rn(ax, ay);
}

// WcT[320][192] + bias[320]
__global__ void prep_weights_kernel(
    const float* __restrict__ W10, const float* __restrict__ b1,
    const float* __restrict__ W20, const float* __restrict__ W21, const float* __restrict__ b2,
    const float* __restrict__ W30, const float* __restrict__ W31, const float* __restrict__ W32,
    const float* __restrict__ b3)
{
    int i = blockIdx.x * blockDim.x + threadIdx.x;
    if (i >= WC_ROWS * WC_COLS) return;
    int k = i / WC_COLS;
    int c = i % WC_COLS;
    float v = 0.f;
    if (k < 64) {
        if (c < 100)       v = W10[k * 100 + c];
        else if (c < 200)  v = W20[k * 100 + (c - 100)];
        else if (c < 300)  v = W30[k * 100 + (c - 200)] - W32[k * 100 + (c - 200)];
    } else if (k < 128) {
        int kk = k - 64;
        if (c >= 100 && c < 200)      v = W21[kk * 100 + (c - 100)];
        else if (c >= 200 && c < 300) v = W31[kk * 100 + (c - 200)];
    } else {
        int kk = k - 128;
        if (c >= 200 && c < 300) v = 2.f * W32[kk * 100 + (c - 200)];
    }
    g_WcT[c * WC_ROWS + k] = v;
    if (i < WC_COLS) {
        float bv = 0.f;
        if (i < 100)      bv = b1[i];
        else if (i < 200) bv = b2[i - 100];
        else if (i < 300) bv = b3[i - 200];
        g_bias[i] = bv;
    }
}

// ---------------- fp16 mma.sync GEMM (single MMA; A staged by direct fp16 copy) ----------------
#define SA_F 0
#define SB_F 18432
#define SM_GEMM 27648

__device__ __forceinline__ uint32_t smem_u32(const void* p) {
    uint32_t a;
    asm("{ .reg .u64 t; cvta.to.shared.u64 t, %1; cvt.u32.u64 %0, t; }" : "=r"(a) : "l"(p));
    return a;
}
__device__ __forceinline__ void ldm_x4(uint32_t& r0, uint32_t& r1, uint32_t& r2, uint32_t& r3, uint32_t a) {
    asm volatile("ldmatrix.sync.aligned.m8n8.x4.shared.b16 {%0,%1,%2,%3}, [%4];"
        : "=r"(r0), "=r"(r1), "=r"(r2), "=r"(r3) : "r"(a));
}
__device__ __forceinline__ void mma_f16(float* d, const uint32_t* a, uint32_t b0, uint32_t b1) {
    asm volatile("mma.sync.aligned.m16n8k16.row.col.f32.f16.f16.f32 "
        "{%0,%1,%2,%3}, {%4,%5,%6,%7}, {%8,%9}, {%0,%1,%2,%3};"
        : "+f"(d[0]), "+f"(d[1]), "+f"(d[2]), "+f"(d[3])
        : "r"(a[0]), "r"(a[1]), "r"(a[2]), "r"(a[3]), "r"(b0), "r"(b1));
}
__device__ __forceinline__ uint2 cvt4h(float4 v) {
    __half2 h01 = __floats2half2_rn(v.x, v.y);
    __half2 h23 = __floats2half2_rn(v.z, v.w);
    uint2 r;
    r.x = *reinterpret_cast<uint32_t*>(&h01);
    r.y = *reinterpret_cast<uint32_t*>(&h23);
    return r;
}

__global__ void __launch_bounds__(256, 2)
gemm_kernel(float* __restrict__ out, int q_base)
{
    extern __shared__ __align__(16) char smem[];
    const uint32_t sb = smem_u32(smem);
    const int tid = threadIdx.x;
    const int wid = tid >> 5;
    const int lane = tid & 31;
    const int wr = wid & 3;
    const int wc = wid >> 2;
    const int tile = blockIdx.x;
    const int q = q_base + blockIdx.y;
    const int nch = (q == 0) ? 1 : (q < 3) ? 2 : 3;

    float acc[2][4][4];
#pragma unroll
    for (int mt = 0; mt < 2; mt++)
#pragma unroll
        for (int nt = 0; nt < 4; nt++)
#pragma unroll
            for (int i = 0; i < 4; i++) acc[mt][nt][i] = 0.f;

    const uint32_t aRowOff = (uint32_t)((wr * 32 + (lane & 15)) * 144 + (lane >> 4) * 16);
    const uint32_t bRowBase = (uint32_t)((wc * 32 + ((lane >> 4) << 3) + (lane & 7)) * 144
                                         + (((lane >> 3) & 1) ? 16 : 0));

    for (int c = 0; c < nch; c++) {
        __syncthreads();
        // stage A: direct fp16 copy (row = 128B)
        const char* ah = (c == 0) ? (const char*)g_xh
                       : (c == 1) ? (const char*)g_T1h
                                  : (const char*)g_T2h;
#pragma unroll
        for (int i = 0; i < 4; i++) {
            int idx = tid + i * 256;          // 0..1023
            int row = idx >> 3;               // 0..127
            int c16 = idx & 7;
            int node = tile * 128 + row;
            uint4 v = make_uint4(0u, 0u, 0u, 0u);
            if (node < N_NODES)
                v = *reinterpret_cast<const uint4*>(ah + (long long)node * 128 + c16 * 16);
            *reinterpret_cast<uint4*>(smem + SA_F + row * 144 + c16 * 16) = v;
        }
        // stage B: 64 cols x 64 k fp32 -> fp16
#pragma unroll
        for (int i = 0; i < 4; i++) {
            int idx = tid + i * 256;          // 0..1023
            int nrow = idx >> 4;              // 0..63
            int f4 = idx & 15;
            float4 v = *reinterpret_cast<const float4*>(
                &g_WcT[(q * 64 + nrow) * WC_ROWS + c * 64 + f4 * 4]);
            uint2 h = cvt4h(v);
            uint32_t off = (uint32_t)(nrow * 144 + f4 * 8);
            *reinterpret_cast<uint2*>(smem + SB_F + off) = h;
        }
        __syncthreads();

#pragma unroll
        for (int ks = 0; ks < 4; ks++) {
            uint32_t k0b = (uint32_t)(ks * 32);
            uint32_t af[2][4];
#pragma unroll
            for (int mt = 0; mt < 2; mt++) {
                uint32_t aoff = aRowOff + (uint32_t)(mt * 16 * 144) + k0b;
                ldm_x4(af[mt][0], af[mt][1], af[mt][2], af[mt][3], sb + SA_F + aoff);
            }
            uint32_t bf[4][2];
#pragma unroll
            for (int g2 = 0; g2 < 2; g2++) {
                uint32_t boff = bRowBase + (uint32_t)(g2 * 16 * 144) + k0b;
                ldm_x4(bf[g2 * 2][0], bf[g2 * 2][1], bf[g2 * 2 + 1][0], bf[g2 * 2 + 1][1],
                       sb + SB_F + boff);
            }
#pragma unroll
            for (int mt = 0; mt < 2; mt++)
#pragma unroll
                for (int nt = 0; nt < 4; nt++)
                    mma_f16(acc[mt][nt], af[mt], bf[nt][0], bf[nt][1]);
        }
    }

    const int g = lane >> 2;
    const int c2 = (lane & 3) * 2;
#pragma unroll
    for (int mt = 0; mt < 2; mt++)
#pragma unroll
        for (int nt = 0; nt < 4; nt++) {
            int col = q * 64 + wc * 32 + nt * 8 + c2;
            if (col >= OUT_COLS) continue;
            float2 bv = *reinterpret_cast<const float2*>(&g_bias[col]);
#pragma unroll
            for (int h = 0; h < 2; h++) {
                int node = tile * 128 + wr * 32 + mt * 16 + g + h * 8;
                if (node < N_NODES) {
                    float2 o = make_float2(acc[mt][nt][h * 2 + 0] + bv.x,
                                           acc[mt][nt][h * 2 + 1] + bv.y);
                    *reinterpret_cast<float2*>(&out[(long long)node * OUT_COLS + col]) = o;
                }
            }
        }
}

// ---------------- launch (multi-stream fork/join, capture-legal) ----------------
extern "C" void kernel_launch(void* const* d_in, const int* in_sizes, int n_in,
                              void* d_out, int out_size)
{
    const float* x = nullptr;
    const void*  ei = nullptr;
    const float* ew = nullptr;
    const float* Ws[6] = {};
    const float* Bs[3] = {};
    int nw = 0, nb = 0;
    for (int i = 0; i < n_in; i++) {
        int s = in_sizes[i];
        if (s == N_NODES * D_IN)      x = (const float*)d_in[i];
        else if (s == 2 * N_EDGES)    ei = d_in[i];
        else if (s == N_EDGES)        ew = (const float*)d_in[i];
        else if (s == D_IN * 100)     { if (nw < 6) Ws[nw++] = (const float*)d_in[i]; }
        else if (s == 100)            { if (nb < 3) Bs[nb++] = (const float*)d_in[i]; }
    }
    if (!x)  x  = (const float*)d_in[0];
    if (!ei) ei = d_in[1];
    if (!ew) ew = (const float*)d_in[2];
    if (nw < 6) {
        Ws[0] = (const float*)d_in[3];  Ws[1] = (const float*)d_in[5];
        Ws[2] = (const float*)d_in[6];  Ws[3] = (const float*)d_in[8];
        Ws[4] = (const float*)d_in[9];  Ws[5] = (const float*)d_in[10];
    }
    if (nb < 3) {
        Bs[0] = (const float*)d_in[4];  Bs[1] = (const float*)d_in[7];
        Bs[2] = (const float*)d_in[11];
    }
    float* out = (float*)d_out;

    cudaFuncSetAttribute(gemm_kernel, cudaFuncAttributeMaxDynamicSharedMemorySize, SM_GEMM);

    const int B = 256;
    const int nodeGrid = (N_NODES + B - 1) / B;
    const int edgeGrid = (N_EDGES + B - 1) / B;
    const int tileGrid = (N_NODES + 127) / 128;

    cudaStream_t s2;
    cudaStreamCreate(&s2);
    cudaEvent_t evFork, evXh, evW, evP0, evJoin;
    cudaEventCreateWithFlags(&evFork, cudaEventDisableTiming);
    cudaEventCreateWithFlags(&evXh,   cudaEventDisableTiming);
    cudaEventCreateWithFlags(&evW,    cudaEventDisableTiming);
    cudaEventCreateWithFlags(&evP0,   cudaEventDisableTiming);
    cudaEventCreateWithFlags(&evJoin, cudaEventDisableTiming);

    // ---- main: CSR build ----
    detect_dtype_kernel<<<1, 256>>>((const int*)ei);
    cudaEventRecord(evFork, 0);

    // ---- side: convert x -> xh, prep weights, GEMM q0 (uses xh) ----
    cudaStreamWaitEvent(s2, evFork, 0);
    convert_x_kernel<<<(N_NODES * 32 + B - 1) / B, B, 0, s2>>>(x);
    cudaEventRecord(evXh, s2);
    prep_weights_kernel<<<(WC_ROWS * WC_COLS + B - 1) / B, B, 0, s2>>>(
        Ws[0], Bs[0], Ws[1], Ws[2], Bs[1], Ws[3], Ws[4], Ws[5], Bs[2]);
    cudaEventRecord(evW, s2);
    {
        dim3 grid(tileGrid, 1);
        gemm_kernel<<<grid, 256, SM_GEMM, s2>>>(out, 0);
    }

    // ---- main continues: CSR build, then props (need xh) ----
    zero_kernel<<<nodeGrid, B>>>();
    deg_hist_kernel<<<edgeGrid, B>>>(ei, ew);
    dis_kernel<<<nodeGrid, B>>>();
    scan1_kernel<<<SCAN_NB, SCAN_BS>>>();
    scan2_kernel<<<1, 128>>>();
    finalize_off_kernel<<<nodeGrid, B>>>();
    fill_kernel<<<edgeGrid, B>>>(ei, ew);
    cudaStreamWaitEvent(0, evXh, 0);
    {
        long long items = (long long)N_NODES * 32;
        int grid = (int)((items + B - 1) / B);
        prop_kernel<<<grid, B>>>(0);     // xh -> T1h
        cudaEventRecord(evP0, 0);
        prop_kernel<<<grid, B>>>(1);     // T1h -> T2h
    }

    // side: q1,q2 need T1h + weights
    cudaStreamWaitEvent(s2, evP0, 0);
    {
        dim3 grid(tileGrid, 2);
        gemm_kernel<<<grid, 256, SM_GEMM, s2>>>(out, 1);
    }
    cudaEventRecord(evJoin, s2);

    // main: q3,q4 need T2h + weights
    cudaStreamWaitEvent(0, evW, 0);
    {
        dim3 grid(tileGrid, 2);
        gemm_kernel<<<grid, 256, SM_GEMM>>>(out, 3);
    }
    cudaStreamWaitEvent(0, evJoin, 0);
}